// round 10
// baseline (speedup 1.0000x reference)
#include <cuda_runtime.h>
#include <cstdint>
#include <math.h>

#define BB 65536
#define FDIM 267
#define HDIM 256
#define LDIM 64
#define KCODE 1024

// pair strides (uint2 per 2 K-elems), K padded to 16-mult, rows padded to grid
#define KU1 272   // fc1: K=534
#define KU2 128   // K=256
#define KU4 176   // fc4: K=331
#define KUM 32    // mu pairs

// ---------------- scratch (device globals) ----------------
__device__ uint2 g_h1p[BB * KU2];
__device__ uint2 g_h2p[BB * KU2];
__device__ uint2 g_mup[BB * KUM];
__device__ float g_mu[BB * LDIM];
__device__ float g_q[BB * LDIM];
__device__ int   g_idx[BB];
__device__ float g_esq[KCODE];
__device__ int   g_counts[KCODE];
__device__ float g_partials[BB / 8];
__device__ uint32_t g_eth[KCODE * 32], g_etl[KCODE * 32];  // codebook pairs [code][l/2]
__device__ uint2 g_w1i[256 * KU1];
__device__ uint2 g_w2i[256 * KU2];
__device__ uint2 g_w3i[256 * KU2];
__device__ uint2 g_wmi[128 * KU2];
__device__ uint2 g_w4i[256 * KU4];
__device__ uint2 g_w5i[256 * KU2];
__device__ uint2 g_w6i[256 * KU2];
__device__ uint2 g_woi[384 * KU2];

// ---------------- helpers ----------------
__device__ __forceinline__ float hi32(float a) {
    return __uint_as_float(__float_as_uint(a) & 0xFFFFE000u);
}
__device__ __forceinline__ uint32_t packh(float x, float y) {
    uint32_t d;
    asm("cvt.rn.f16x2.f32 %0, %1, %2;" : "=r"(d) : "f"(y), "f"(x));
    return d;
}
__device__ __forceinline__ uint32_t split_pack(float a, float b, uint32_t& lo) {
    float ha = hi32(a), hb = hi32(b);
    lo = packh(a - ha, b - hb);
    return packh(ha, hb);
}
__device__ __forceinline__ uint32_t smem_u32(const void* p) {
    uint32_t a;
    asm("{ .reg .u64 t; cvta.to.shared.u64 t, %1; cvt.u32.u64 %0, t; }" : "=r"(a) : "l"(p));
    return a;
}
__device__ __forceinline__ void ldm_x4(uint32_t* d, uint32_t a) {
    asm volatile("ldmatrix.sync.aligned.m8n8.x4.shared.b16 {%0,%1,%2,%3}, [%4];"
        : "=r"(d[0]), "=r"(d[1]), "=r"(d[2]), "=r"(d[3]) : "r"(a));
}
__device__ __forceinline__ void mma16(float* d, const uint32_t* a, const uint32_t* b) {
    asm volatile(
        "mma.sync.aligned.m16n8k16.row.col.f32.f16.f16.f32 "
        "{%0,%1,%2,%3},{%4,%5,%6,%7},{%8,%9},{%0,%1,%2,%3};"
        : "+f"(d[0]), "+f"(d[1]), "+f"(d[2]), "+f"(d[3])
        : "r"(a[0]), "r"(a[1]), "r"(a[2]), "r"(a[3]), "r"(b[0]), "r"(b[1]));
}

// ---------------- fp16x3 HMMA GEMM ----------------
// C = act(A * W^T + b). 128x128 CTA tile, BK=32, 16 warps (4m x 4n), warp tile 32x32.
// A: pre-split uint2 pairs (Ap) OR fp32 concat [A0|A1] split on the fly.
// B: pre-split interleaved uint2 pairs (padded). Output: fp32 (Cf) and/or pairs (Cp).
// smem u32 per buf: Ahi[128][20] | Alo | Bhi | Blo = 10240; 2 bufs = 81920 B.
__global__ void __launch_bounds__(512, 1) mma_gemm(
    const float* __restrict__ A0, int W0,
    const float* __restrict__ A1, int W1,
    const uint2* __restrict__ Ap,
    const uint2* __restrict__ Wt, int KUb,
    const float* __restrict__ bias,
    float* __restrict__ Cf, uint2* __restrict__ Cp, int NUp,
    int N, int K, int relu)
{
    extern __shared__ uint32_t smu[];

    const int tid = threadIdx.x, lane = tid & 31, wid = tid >> 5;
    const int m0 = blockIdx.y * 128, bn = blockIdx.x * 128;
    const int wm0 = (wid >> 2) * 32, wn0 = (wid & 3) * 32;
    const int r = lane >> 2, kq = lane & 3;
    const int NC = (K + 31) >> 5;
    const int prow = tid >> 4;     // 0..31 loader row
    const int pj   = tid & 15;     // u32 col (half2 pair index)
    const bool scalA = (A1 != nullptr);
    const bool pairsA = (Ap != nullptr);

    // ldmatrix lane addresses (buffer 0)
    const uint32_t sbase = smem_u32(smu);
    const int g = lane >> 3, lr = lane & 7;
    uint32_t aA[2][2], aB[2][2];
    #pragma unroll
    for (int mt = 0; mt < 2; mt++) {
        const uint32_t row = wm0 + mt * 16 + (g & 1) * 8 + lr;
        const uint32_t col = (g >> 1) * 4;
        #pragma unroll
        for (int ks = 0; ks < 2; ks++)
            aA[mt][ks] = sbase + 4u * (row * 20 + col + ks * 8);
    }
    #pragma unroll
    for (int np = 0; np < 2; np++) {
        const uint32_t n = wn0 + (2 * np + (g >> 1)) * 8 + lr;
        const uint32_t col = (g & 1) * 4;
        #pragma unroll
        for (int ks = 0; ks < 2; ks++)
            aB[np][ks] = sbase + 4u * (5120 + n * 20 + col + ks * 8);
    }

    float acc[2][4][4];
    #pragma unroll
    for (int i = 0; i < 2; i++)
        #pragma unroll
        for (int j = 0; j < 4; j++)
            #pragma unroll
            for (int e = 0; e < 4; e++) acc[i][j][e] = 0.f;

    float2 a2[4];
    uint2  aw[4], bw[4];

    auto prefetch = [&](int c) {
        const size_t bo = (size_t)c * 16 + pj;
        const int kg = c * 32 + 2 * pj;
        #pragma unroll
        for (int p = 0; p < 4; p++) {
            const int row = p * 32 + prow;
            if (pairsA) {
                aw[p] = Ap[(size_t)(m0 + row) * KUb + bo];
            } else {
                float ax = 0.f, ay = 0.f;
                if (scalA) {
                    if (kg < K)
                        ax = (kg < W0) ? A0[(size_t)(m0 + row) * W0 + kg]
                                       : A1[(size_t)(m0 + row) * W1 + (kg - W0)];
                    if (kg + 1 < K)
                        ay = (kg + 1 < W0) ? A0[(size_t)(m0 + row) * W0 + kg + 1]
                                           : A1[(size_t)(m0 + row) * W1 + (kg + 1 - W0)];
                } else if (kg < K) {
                    float2 t = *(const float2*)&A0[(size_t)(m0 + row) * W0 + kg];
                    ax = t.x; ay = t.y;
                }
                a2[p] = make_float2(ax, ay);
            }
            bw[p] = Wt[(size_t)(bn + row) * KUb + bo];
        }
    };
    auto store = [&](int b) {
        uint32_t* base = smu + b * 10240;
        #pragma unroll
        for (int p = 0; p < 4; p++) {
            const int o = (p * 32 + prow) * 20 + pj;
            if (pairsA) {
                base[o]        = aw[p].x;
                base[2560 + o] = aw[p].y;
            } else {
                float hx = hi32(a2[p].x), hy = hi32(a2[p].y);
                base[o]        = packh(hx, hy);
                base[2560 + o] = packh(a2[p].x - hx, a2[p].y - hy);
            }
            base[5120 + o] = bw[p].x;
            base[7680 + o] = bw[p].y;
        }
    };
    auto compute = [&]() {
        #pragma unroll
        for (int ks = 0; ks < 2; ks++) {
            uint32_t ah[2][4], al[2][4], bh[4][2], bl[4][2];
            ldm_x4(ah[0], aA[0][ks]);
            ldm_x4(ah[1], aA[1][ks]);
            ldm_x4(al[0], aA[0][ks] + 10240u);
            ldm_x4(al[1], aA[1][ks] + 10240u);
            ldm_x4(&bh[0][0], aB[0][ks]);
            ldm_x4(&bh[2][0], aB[1][ks]);
            ldm_x4(&bl[0][0], aB[0][ks] + 10240u);
            ldm_x4(&bl[2][0], aB[1][ks] + 10240u);
            #pragma unroll
            for (int mt = 0; mt < 2; mt++)
                #pragma unroll
                for (int nt = 0; nt < 4; nt++) {
                    mma16(acc[mt][nt], ah[mt], bh[nt]);
                    mma16(acc[mt][nt], ah[mt], bl[nt]);
                    mma16(acc[mt][nt], al[mt], bh[nt]);
                }
        }
    };

    prefetch(0); store(0); __syncthreads();
    int32_t dshift = 40960;
    for (int c = 0; c < NC; c++) {
        if (c + 1 < NC) prefetch(c + 1);
        compute();
        if (c + 1 < NC) store((c + 1) & 1);
        __syncthreads();
        if (c + 1 < NC) {
            #pragma unroll
            for (int mt = 0; mt < 2; mt++)
                #pragma unroll
                for (int ks = 0; ks < 2; ks++) { aA[mt][ks] += dshift; aB[mt][ks] += dshift; }
            dshift = -dshift;
        }
    }

    // epilogue: bias + relu; optional fp32 and/or pair outputs
    const bool evenN = (N & 1) == 0;
    #pragma unroll
    for (int mt = 0; mt < 2; mt++) {
        #pragma unroll
        for (int q = 0; q < 2; q++) {
            const int row = m0 + wm0 + mt * 16 + q * 8 + r;
            #pragma unroll
            for (int nt = 0; nt < 4; nt++) {
                const int n = bn + wn0 + nt * 8 + 2 * kq;
                float v0 = acc[mt][nt][q * 2 + 0];
                float v1 = acc[mt][nt][q * 2 + 1];
                if (n + 1 < N) {
                    float o0 = v0 + bias[n];
                    float o1 = v1 + bias[n + 1];
                    if (relu) { o0 = fmaxf(o0, 0.f); o1 = fmaxf(o1, 0.f); }
                    if (Cp) {
                        uint32_t l; uint32_t h = split_pack(o0, o1, l);
                        Cp[(size_t)row * NUp + (n >> 1)] = make_uint2(h, l);
                    }
                    if (Cf) {
                        if (evenN) {
                            float2 p; p.x = o0; p.y = o1;
                            *(float2*)&Cf[(size_t)row * N + n] = p;
                        } else {
                            Cf[(size_t)row * N + n] = o0;
                            Cf[(size_t)row * N + n + 1] = o1;
                        }
                    }
                } else if (n < N && Cf) {
                    float o0 = v0 + bias[n];
                    if (relu) o0 = fmaxf(o0, 0.f);
                    Cf[(size_t)row * N + n] = o0;
                }
            }
        }
    }
}

// ---------------- VQ argmin via fp16x3 HMMA + ldmatrix, 512 threads ----------------
// 128 rows/CTA, 8 code-tiles of 128, K=64. 16 warps: 4 row-groups x 4 code-quarters.
// score = esq[k] - 2*mu.e_k ; ties -> lowest index.
__global__ void __launch_bounds__(512, 1) vq_mma()
{
    extern __shared__ uint32_t smv[];
    uint32_t* Mh = smv;             // [128][36]
    uint32_t* Ml = smv + 4608;
    uint32_t* Eh = smv + 9216;
    uint32_t* El = smv + 13824;
    float* esq_s = (float*)(smv + 18432);

    __shared__ float sbest[16][2][2][8];
    __shared__ int   sidx[16][2][2][8];

    const int tid = threadIdx.x, lane = tid & 31, wid = tid >> 5;
    const int m0 = blockIdx.x * 128;
    const int wm0 = (wid >> 2) * 32;
    const int wq  = wid & 3;
    const int wn0 = wq * 32;
    const int r = lane >> 2, kq = lane & 3;

    const uint32_t sbase = smem_u32(smv);
    const int g = lane >> 3, lr = lane & 7;
    uint32_t aM[2], aE[2];
    #pragma unroll
    for (int mt = 0; mt < 2; mt++) {
        const uint32_t row = wm0 + mt * 16 + (g & 1) * 8 + lr;
        aM[mt] = sbase + 4u * (row * 36 + (g >> 1) * 4);
    }
    #pragma unroll
    for (int np = 0; np < 2; np++) {
        const uint32_t n = wn0 + (2 * np + (g >> 1)) * 8 + lr;
        aE[np] = sbase + 4u * (9216 + n * 36 + (g & 1) * 4);
    }

    // mu pairs from producer epilogue: 8 passes of 16 rows
    #pragma unroll
    for (int ps = 0; ps < 8; ps++) {
        const int row = ps * 16 + wid;
        uint2 t = g_mup[(size_t)(m0 + row) * KUM + lane];
        Mh[row * 36 + lane] = t.x;
        Ml[row * 36 + lane] = t.y;
    }
    #pragma unroll
    for (int i = tid; i < KCODE; i += 512) esq_s[i] = g_esq[i];

    float best[2][2];
    int   bidx[2][2];
    #pragma unroll
    for (int i = 0; i < 2; i++)
        #pragma unroll
        for (int j = 0; j < 2; j++) { best[i][j] = 3.4e38f; bidx[i][j] = 0; }

    uint32_t uh[8], ul[8];
    for (int ct = 0; ct < 8; ct++) {
        // prefetch pre-split code tile to regs
        #pragma unroll
        for (int ps = 0; ps < 8; ps++) {
            const int row = ps * 16 + wid;
            uh[ps] = g_eth[(size_t)(ct * 128 + row) * 32 + lane];
            ul[ps] = g_etl[(size_t)(ct * 128 + row) * 32 + lane];
        }
        __syncthreads();   // prior compute done reading E (also covers mu/esq on ct=0)
        #pragma unroll
        for (int ps = 0; ps < 8; ps++) {
            const int row = ps * 16 + wid;
            Eh[row * 36 + lane] = uh[ps];
            El[row * 36 + lane] = ul[ps];
        }
        __syncthreads();

        float acc[2][4][4];
        #pragma unroll
        for (int i = 0; i < 2; i++)
            #pragma unroll
            for (int j = 0; j < 4; j++)
                #pragma unroll
                for (int e = 0; e < 4; e++) acc[i][j][e] = 0.f;

        #pragma unroll
        for (int ks = 0; ks < 4; ks++) {
            const uint32_t ko = ks * 32u;
            uint32_t ah[2][4], al[2][4], bh[4][2], bl[4][2];
            ldm_x4(ah[0], aM[0] + ko);
            ldm_x4(ah[1], aM[1] + ko);
            ldm_x4(al[0], aM[0] + ko + 18432u);
            ldm_x4(al[1], aM[1] + ko + 18432u);
            ldm_x4(&bh[0][0], aE[0] + ko);
            ldm_x4(&bh[2][0], aE[1] + ko);
            ldm_x4(&bl[0][0], aE[0] + ko + 18432u);
            ldm_x4(&bl[2][0], aE[1] + ko + 18432u);
            #pragma unroll
            for (int mt = 0; mt < 2; mt++)
                #pragma unroll
                for (int nt = 0; nt < 4; nt++) {
                    mma16(acc[mt][nt], ah[mt], bh[nt]);
                    mma16(acc[mt][nt], ah[mt], bl[nt]);
                    mma16(acc[mt][nt], al[mt], bh[nt]);
                }
        }

        // score + argmin update (ascending code order; strict < keeps first min)
        #pragma unroll
        for (int mt = 0; mt < 2; mt++)
            #pragma unroll
            for (int q = 0; q < 2; q++)
                #pragma unroll
                for (int nt = 0; nt < 4; nt++)
                    #pragma unroll
                    for (int e = 0; e < 2; e++) {
                        const int code = ct * 128 + wn0 + nt * 8 + 2 * kq + e;
                        const float sc = esq_s[code] - 2.f * acc[mt][nt][q * 2 + e];
                        if (sc < best[mt][q]) { best[mt][q] = sc; bidx[mt][q] = code; }
                    }
        __syncthreads();
    }

    // 1) reduce across the 4 lanes of each quad (same rows, different code subsets)
    #pragma unroll
    for (int mt = 0; mt < 2; mt++)
        #pragma unroll
        for (int q = 0; q < 2; q++) {
            float b = best[mt][q]; int ix = bidx[mt][q];
            #pragma unroll
            for (int s = 1; s <= 2; s <<= 1) {
                const float ob = __shfl_xor_sync(0xffffffffu, b, s);
                const int   oi = __shfl_xor_sync(0xffffffffu, ix, s);
                if (ob < b || (ob == b && oi < ix)) { b = ob; ix = oi; }
            }
            if (kq == 0) { sbest[wid][mt][q][r] = b; sidx[wid][mt][q][r] = ix; }
        }
    __syncthreads();

    // 2) merge the 4 code-quarter warps of each row group, write final index
    if (wq == 0 && kq == 0) {
        #pragma unroll
        for (int mt = 0; mt < 2; mt++)
            #pragma unroll
            for (int q = 0; q < 2; q++) {
                float b0 = sbest[wid][mt][q][r]; int i0 = sidx[wid][mt][q][r];
                #pragma unroll
                for (int w2 = 1; w2 < 4; w2++) {
                    float b1 = sbest[wid + w2][mt][q][r]; int i1 = sidx[wid + w2][mt][q][r];
                    if (b1 < b0 || (b1 == b0 && i1 < i0)) { b0 = b1; i0 = i1; }
                }
                g_idx[m0 + wm0 + mt * 16 + r + q * 8] = i0;
            }
    }
}

// ---------------- prep kernels ----------------
__global__ void wsplit2(const float* __restrict__ W, uint2* __restrict__ out,
                        int N, int K, int KU, int total)
{
    int i = blockIdx.x * 256 + threadIdx.x;
    if (i >= total) return;
    int n = i / KU, j = i - n * KU;
    int k0 = 2 * j;
    float a = (n < N && k0 < K) ? W[(size_t)n * K + k0] : 0.f;
    float b = (n < N && k0 + 1 < K) ? W[(size_t)n * K + k0 + 1] : 0.f;
    uint32_t l; uint32_t h = split_pack(a, b, l);
    out[i] = make_uint2(h, l);
}
__global__ void et_split(const float* __restrict__ embed)
{
    int i = blockIdx.x * 256 + threadIdx.x;
    if (i >= KCODE * 32) return;
    int code = i >> 5, j = i & 31;
    float a = embed[(2 * j) * KCODE + code];
    float b = embed[(2 * j + 1) * KCODE + code];
    uint32_t l; uint32_t h = split_pack(a, b, l);
    g_eth[i] = h; g_etl[i] = l;
}
__global__ void esq_kernel(const float* __restrict__ embed) {
    int k = blockIdx.x * blockDim.x + threadIdx.x;
    if (k < KCODE) {
        float s = 0.f;
        #pragma unroll 8
        for (int l = 0; l < LDIM; l++) { float e = embed[l * KCODE + k]; s += e * e; }
        g_esq[k] = s;
    }
}
__global__ void zero_counts_kernel() {
    int i = blockIdx.x * blockDim.x + threadIdx.x;
    if (i < KCODE) g_counts[i] = 0;
}

__global__ void __launch_bounds__(256) gather_loss_kernel(const float* __restrict__ embed) {
    __shared__ float ps[8];
    const int w = threadIdx.x >> 5, lane = threadIdx.x & 31;
    const int row = blockIdx.x * 8 + w;
    const int idx = g_idx[row];
    float s = 0.f;
    #pragma unroll
    for (int h = 0; h < 2; h++) {
        int l = lane + 32 * h;
        float e = embed[l * KCODE + idx];
        g_q[(size_t)row * LDIM + l] = e;
        float d = e - g_mu[(size_t)row * LDIM + l];
        s += d * d;
    }
    #pragma unroll
    for (int off = 16; off; off >>= 1) s += __shfl_down_sync(0xffffffffu, s, off);
    if (lane == 0) { ps[w] = s; atomicAdd(&g_counts[idx], 1); }
    __syncthreads();
    if (threadIdx.x == 0) {
        float t = 0.f;
        #pragma unroll
        for (int i = 0; i < 8; i++) t += ps[i];
        g_partials[blockIdx.x] = t;
    }
}

__global__ void __launch_bounds__(256) finalize_kernel(float* __restrict__ out) {
    __shared__ float red[256];
    const int t = threadIdx.x;
    float s = 0.f;
    for (int i = t; i < BB / 8; i += 256) s += g_partials[i];
    red[t] = s;
    for (int st = 128; st > 0; st >>= 1) { __syncthreads(); if (t < st) red[t] += red[t + st]; }
    __syncthreads();
    float loss = red[0] / (float)((size_t)BB * LDIM);
    __syncthreads();
    float e = 0.f;
    for (int k = t; k < KCODE; k += 256) {
        float p = (float)g_counts[k] / (float)BB;
        e += p * logf(p + 1e-10f);
    }
    red[t] = e;
    for (int st = 128; st > 0; st >>= 1) { __syncthreads(); if (t < st) red[t] += red[t + st]; }
    __syncthreads();
    if (t == 0) {
        out[(size_t)BB * FDIM] = loss;
        out[(size_t)BB * FDIM + 1] = expf(-red[0]);
    }
}

// ---------------- host launcher ----------------
#define SYM(v, s) cudaGetSymbolAddress((void**)&v, s)

extern "C" void kernel_launch(void* const* d_in, const int* in_sizes, int n_in,
                              void* d_out, int out_size)
{
    const float* x     = (const float*)d_in[0];
    const float* c     = (const float*)d_in[1];
    const float* fc1_w = (const float*)d_in[2];
    const float* fc1_b = (const float*)d_in[3];
    const float* fc2_w = (const float*)d_in[4];
    const float* fc2_b = (const float*)d_in[5];
    const float* fc3_w = (const float*)d_in[6];
    const float* fc3_b = (const float*)d_in[7];
    const float* mu_w  = (const float*)d_in[8];
    const float* mu_b  = (const float*)d_in[9];
    const float* fc4_w = (const float*)d_in[10];
    const float* fc4_b = (const float*)d_in[11];
    const float* fc5_w = (const float*)d_in[12];
    const float* fc5_b = (const float*)d_in[13];
    const float* fc6_w = (const float*)d_in[14];
    const float* fc6_b = (const float*)d_in[15];
    const float* out_w = (const float*)d_in[16];
    const float* out_b = (const float*)d_in[17];
    const float* embed = (const float*)d_in[18];
    float* out = (float*)d_out;

    float *mu, *q;
    uint2 *h1p, *h2p, *mup;
    uint2 *w1i, *w2i, *w3i, *wmi, *w4i, *w5i, *w6i, *woi;
    SYM(mu, g_mu); SYM(q, g_q);
    SYM(h1p, g_h1p); SYM(h2p, g_h2p); SYM(mup, g_mup);
    SYM(w1i, g_w1i); SYM(w2i, g_w2i); SYM(w3i, g_w3i); SYM(wmi, g_wmi);
    SYM(w4i, g_w4i); SYM(w5i, g_w5i); SYM(w6i, g_w6i); SYM(woi, g_woi);

    const int GEMM_SMEM = 2 * 10240 * 4;            // 81920 B
    const int VQ_SMEM   = (18432 + 1024) * 4;       // 77824 B
    cudaFuncSetAttribute(mma_gemm, cudaFuncAttributeMaxDynamicSharedMemorySize, GEMM_SMEM);
    cudaFuncSetAttribute(vq_mma,   cudaFuncAttributeMaxDynamicSharedMemorySize, VQ_SMEM);

    const dim3 blk(512);
    const dim3 g256(2, BB / 128);
    const dim3 g64(1, BB / 128);
    const dim3 g267(3, BB / 128);

    // prep: weight/codebook splits (tiny)
    wsplit2<<<(256 * KU1 + 255) / 256, 256>>>(fc1_w, w1i, 256, 534, KU1, 256 * KU1);
    wsplit2<<<(256 * KU2 + 255) / 256, 256>>>(fc2_w, w2i, 256, 256, KU2, 256 * KU2);
    wsplit2<<<(256 * KU2 + 255) / 256, 256>>>(fc3_w, w3i, 256, 256, KU2, 256 * KU2);
    wsplit2<<<(128 * KU2 + 255) / 256, 256>>>(mu_w,  wmi, 64,  256, KU2, 128 * KU2);
    wsplit2<<<(256 * KU4 + 255) / 256, 256>>>(fc4_w, w4i, 256, 331, KU4, 256 * KU4);
    wsplit2<<<(256 * KU2 + 255) / 256, 256>>>(fc5_w, w5i, 256, 256, KU2, 256 * KU2);
    wsplit2<<<(256 * KU2 + 255) / 256, 256>>>(fc6_w, w6i, 256, 256, KU2, 256 * KU2);
    wsplit2<<<(384 * KU2 + 255) / 256, 256>>>(out_w, woi, 267, 256, KU2, 384 * KU2);
    et_split<<<(KCODE * 32 + 255) / 256, 256>>>(embed);
    esq_kernel<<<4, 256>>>(embed);
    zero_counts_kernel<<<4, 256>>>();

    // encoder
    mma_gemm<<<g256, blk, GEMM_SMEM>>>(x, FDIM, c, FDIM, nullptr, w1i, KU1, fc1_b,
                                       nullptr, h1p, KU2, HDIM, 534, 1);
    mma_gemm<<<g256, blk, GEMM_SMEM>>>(nullptr, 0, nullptr, 0, h1p, w2i, KU2, fc2_b,
                                       nullptr, h2p, KU2, HDIM, HDIM, 1);
    mma_gemm<<<g256, blk, GEMM_SMEM>>>(nullptr, 0, nullptr, 0, h2p, w3i, KU2, fc3_b,
                                       nullptr, h1p, KU2, HDIM, HDIM, 1);
    mma_gemm<<<g64,  blk, GEMM_SMEM>>>(nullptr, 0, nullptr, 0, h1p, wmi, KU2, mu_b,
                                       mu, mup, KUM, LDIM, HDIM, 0);

    // vector quantizer
    vq_mma<<<BB / 128, 512, VQ_SMEM>>>();
    gather_loss_kernel<<<BB / 8, 256>>>(embed);

    // decoder
    mma_gemm<<<g256, blk, GEMM_SMEM>>>(q, LDIM, c, FDIM, nullptr, w4i, KU4, fc4_b,
                                       nullptr, h2p, KU2, HDIM, 331, 1);
    mma_gemm<<<g256, blk, GEMM_SMEM>>>(nullptr, 0, nullptr, 0, h2p, w5i, KU2, fc5_b,
                                       nullptr, h1p, KU2, HDIM, HDIM, 1);
    mma_gemm<<<g256, blk, GEMM_SMEM>>>(nullptr, 0, nullptr, 0, h1p, w6i, KU2, fc6_b,
                                       nullptr, h2p, KU2, HDIM, HDIM, 1);
    mma_gemm<<<g267, blk, GEMM_SMEM>>>(nullptr, 0, nullptr, 0, h2p, woi, KU2, out_b,
                                       out, nullptr, 0, FDIM, HDIM, 0);

    // scalars
    finalize_kernel<<<1, 256>>>(out);
}

// round 11
// speedup vs baseline: 1.0471x; 1.0471x over previous
#include <cuda_runtime.h>
#include <cstdint>
#include <math.h>

#define BB 65536
#define FDIM 267
#define HDIM 256
#define LDIM 64
#define KCODE 1024

// weight pair strides (uint2 per 2 K-elems), K padded to 32-pair (64-elem) chunk multiples
#define KU1 288   // fc1: K=534 -> 9 chunks
#define KU2 128   // K=256 -> 4 chunks
#define KU4 192   // fc4: K=331 -> 6 chunks

// ---------------- scratch (device globals) ----------------
__device__ float g_h1[BB * HDIM];
__device__ float g_h2[BB * HDIM];
__device__ float g_mu[BB * LDIM];
__device__ float g_q[BB * LDIM];
__device__ int   g_idx[BB];
__device__ float g_esq[KCODE];
__device__ int   g_counts[KCODE];
__device__ float g_partials[BB / 8];
__device__ uint32_t g_eth[KCODE * 32], g_etl[KCODE * 32];  // codebook pairs [code][l/2]
__device__ uint2 g_w1i[256 * KU1];
__device__ uint2 g_w2i[256 * KU2];
__device__ uint2 g_w3i[256 * KU2];
__device__ uint2 g_wmi[128 * KU2];
__device__ uint2 g_w4i[256 * KU4];
__device__ uint2 g_w5i[256 * KU2];
__device__ uint2 g_w6i[256 * KU2];
__device__ uint2 g_woi[384 * KU2];

// ---------------- helpers ----------------
__device__ __forceinline__ float hi32(float a) {
    return __uint_as_float(__float_as_uint(a) & 0xFFFFE000u);
}
__device__ __forceinline__ uint32_t packh(float x, float y) {
    uint32_t d;
    asm("cvt.rn.f16x2.f32 %0, %1, %2;" : "=r"(d) : "f"(y), "f"(x));
    return d;
}
__device__ __forceinline__ uint32_t split_pack(float a, float b, uint32_t& lo) {
    float ha = hi32(a), hb = hi32(b);
    lo = packh(a - ha, b - hb);
    return packh(ha, hb);
}
__device__ __forceinline__ uint32_t smem_u32(const void* p) {
    uint32_t a;
    asm("{ .reg .u64 t; cvta.to.shared.u64 t, %1; cvt.u32.u64 %0, t; }" : "=r"(a) : "l"(p));
    return a;
}
__device__ __forceinline__ void ldm_x4(uint32_t* d, uint32_t a) {
    asm volatile("ldmatrix.sync.aligned.m8n8.x4.shared.b16 {%0,%1,%2,%3}, [%4];"
        : "=r"(d[0]), "=r"(d[1]), "=r"(d[2]), "=r"(d[3]) : "r"(a));
}
__device__ __forceinline__ void mma16(float* d, const uint32_t* a, const uint32_t* b) {
    asm volatile(
        "mma.sync.aligned.m16n8k16.row.col.f32.f16.f16.f32 "
        "{%0,%1,%2,%3},{%4,%5,%6,%7},{%8,%9},{%0,%1,%2,%3};"
        : "+f"(d[0]), "+f"(d[1]), "+f"(d[2]), "+f"(d[3])
        : "r"(a[0]), "r"(a[1]), "r"(a[2]), "r"(a[3]), "r"(b[0]), "r"(b[1]));
}

// ---------------- fp16x3 HMMA GEMM: C[M,N] = act([A0|A1][M,K] * Wt^T + b) ----------------
// 128x128 CTA tile, BK=64, 16 warps (4m x 4n), warp tile 32x32.
// A: fp32 global, split on the fly. B: pre-split interleaved uint2 pairs (padded).
// smem u32 per buf: Ahi[128][36] | Alo | Bhi | Blo = 18432; 2 bufs = 147456 B.
__global__ void __launch_bounds__(512, 1) mma_gemm(
    const float* __restrict__ A0, int W0,
    const float* __restrict__ A1, int W1,
    const uint2* __restrict__ Wt, int KUb,
    const float* __restrict__ bias,
    float* __restrict__ C, int N, int K, int relu)
{
    extern __shared__ uint32_t smu[];

    const int tid = threadIdx.x, lane = tid & 31, wid = tid >> 5;
    const int m0 = blockIdx.y * 128, bn = blockIdx.x * 128;
    const int wm0 = (wid >> 2) * 32, wn0 = (wid & 3) * 32;
    const int r = lane >> 2, kq = lane & 3;
    const int NC = (K + 63) >> 6;
    const int prow = tid >> 4;     // 0..31 loader row
    const int pj   = tid & 15;     // segment index (4 fp32 / 2 pair-u32 wide)
    const bool scalA = (A1 != nullptr);

    // ldmatrix lane addresses (buffer 0); row stride 36 u32 (16B-aligned, conflict-free)
    const uint32_t sbase = smem_u32(smu);
    const int g = lane >> 3, lr = lane & 7;
    uint32_t aA[2], aB[2];
    #pragma unroll
    for (int mt = 0; mt < 2; mt++) {
        const uint32_t row = wm0 + mt * 16 + (g & 1) * 8 + lr;
        aA[mt] = sbase + 4u * (row * 36 + (g >> 1) * 4);
    }
    #pragma unroll
    for (int np = 0; np < 2; np++) {
        const uint32_t n = wn0 + (2 * np + (g >> 1)) * 8 + lr;
        aB[np] = sbase + 4u * (9216 + n * 36 + (g & 1) * 4);
    }

    float acc[2][4][4];
    #pragma unroll
    for (int i = 0; i < 2; i++)
        #pragma unroll
        for (int j = 0; j < 4; j++)
            #pragma unroll
            for (int e = 0; e < 4; e++) acc[i][j][e] = 0.f;

    float4 a4[4];
    uint4  b4[4];

    auto prefetch = [&](int c) {
        const int kg0 = c * 64 + 4 * pj;
        const size_t bo = (size_t)c * 32 + 2 * pj;
        #pragma unroll
        for (int p = 0; p < 4; p++) {
            const int row = p * 32 + prow;
            if (scalA) {
                float v[4];
                #pragma unroll
                for (int e = 0; e < 4; e++) {
                    const int kg = kg0 + e;
                    float t = 0.f;
                    if (kg < K)
                        t = (kg < W0) ? A0[(size_t)(m0 + row) * W0 + kg]
                                      : A1[(size_t)(m0 + row) * W1 + (kg - W0)];
                    v[e] = t;
                }
                a4[p] = make_float4(v[0], v[1], v[2], v[3]);
            } else {
                a4[p] = *(const float4*)&A0[(size_t)(m0 + row) * W0 + kg0];
            }
            b4[p] = *(const uint4*)&Wt[(size_t)(bn + row) * KUb + bo];
        }
    };
    auto store = [&](int b) {
        uint32_t* base = smu + b * 18432;
        #pragma unroll
        for (int p = 0; p < 4; p++) {
            const int o = (p * 32 + prow) * 36 + 2 * pj;
            const float h0 = hi32(a4[p].x), h1 = hi32(a4[p].y);
            const float h2 = hi32(a4[p].z), h3 = hi32(a4[p].w);
            base[o]            = packh(h0, h1);
            base[o + 1]        = packh(h2, h3);
            base[4608 + o]     = packh(a4[p].x - h0, a4[p].y - h1);
            base[4608 + o + 1] = packh(a4[p].z - h2, a4[p].w - h3);
            base[9216 + o]      = b4[p].x;
            base[9216 + o + 1]  = b4[p].z;
            base[13824 + o]     = b4[p].y;
            base[13824 + o + 1] = b4[p].w;
        }
    };
    auto compute = [&]() {
        #pragma unroll
        for (int ks = 0; ks < 4; ks++) {
            const uint32_t ko = ks * 32u;      // 8 u32 per ks step
            uint32_t ah[2][4], al[2][4], bh[4][2], bl[4][2];
            ldm_x4(ah[0], aA[0] + ko);
            ldm_x4(ah[1], aA[1] + ko);
            ldm_x4(al[0], aA[0] + ko + 18432u);   // +4608 u32
            ldm_x4(al[1], aA[1] + ko + 18432u);
            ldm_x4(&bh[0][0], aB[0] + ko);
            ldm_x4(&bh[2][0], aB[1] + ko);
            ldm_x4(&bl[0][0], aB[0] + ko + 18432u);
            ldm_x4(&bl[2][0], aB[1] + ko + 18432u);
            #pragma unroll
            for (int mt = 0; mt < 2; mt++)
                #pragma unroll
                for (int nt = 0; nt < 4; nt++) {
                    mma16(acc[mt][nt], ah[mt], bh[nt]);
                    mma16(acc[mt][nt], ah[mt], bl[nt]);
                    mma16(acc[mt][nt], al[mt], bh[nt]);
                }
        }
    };

    prefetch(0); store(0); __syncthreads();
    int32_t dshift = 73728;
    for (int c = 0; c < NC; c++) {
        if (c + 1 < NC) prefetch(c + 1);
        compute();
        if (c + 1 < NC) store((c + 1) & 1);
        __syncthreads();
        if (c + 1 < NC) {
            aA[0] += dshift; aA[1] += dshift;
            aB[0] += dshift; aB[1] += dshift;
            dshift = -dshift;
        }
    }

    // epilogue: bias + relu, float2 stores when aligned
    const bool evenN = (N & 1) == 0;
    #pragma unroll
    for (int mt = 0; mt < 2; mt++) {
        #pragma unroll
        for (int q = 0; q < 2; q++) {
            const int row = m0 + wm0 + mt * 16 + q * 8 + r;
            #pragma unroll
            for (int nt = 0; nt < 4; nt++) {
                const int n = bn + wn0 + nt * 8 + 2 * kq;
                float v0 = acc[mt][nt][q * 2 + 0];
                float v1 = acc[mt][nt][q * 2 + 1];
                if (n + 1 < N) {
                    float o0 = v0 + bias[n];
                    float o1 = v1 + bias[n + 1];
                    if (relu) { o0 = fmaxf(o0, 0.f); o1 = fmaxf(o1, 0.f); }
                    if (evenN) {
                        float2 p; p.x = o0; p.y = o1;
                        *(float2*)&C[(size_t)row * N + n] = p;
                    } else {
                        C[(size_t)row * N + n] = o0;
                        C[(size_t)row * N + n + 1] = o1;
                    }
                } else if (n < N) {
                    float o0 = v0 + bias[n];
                    if (relu) o0 = fmaxf(o0, 0.f);
                    C[(size_t)row * N + n] = o0;
                }
            }
        }
    }
}

// ---------------- VQ argmin via fp16x3 HMMA + ldmatrix, 512 threads ----------------
// 128 rows/CTA, 8 code-tiles of 128, K=64. 16 warps: 4 row-groups x 4 code-quarters.
// score = esq[k] - 2*mu.e_k ; ties -> lowest index.
__global__ void __launch_bounds__(512, 1) vq_mma()
{
    extern __shared__ uint32_t smv[];
    uint32_t* Mh = smv;             // [128][36]
    uint32_t* Ml = smv + 4608;
    uint32_t* Eh = smv + 9216;
    uint32_t* El = smv + 13824;
    float* esq_s = (float*)(smv + 18432);

    __shared__ float sbest[16][2][2][8];
    __shared__ int   sidx[16][2][2][8];

    const int tid = threadIdx.x, lane = tid & 31, wid = tid >> 5;
    const int m0 = blockIdx.x * 128;
    const int wm0 = (wid >> 2) * 32;
    const int wq  = wid & 3;
    const int wn0 = wq * 32;
    const int r = lane >> 2, kq = lane & 3;

    const uint32_t sbase = smem_u32(smv);
    const int g = lane >> 3, lr = lane & 7;
    uint32_t aM[2], aE[2];
    #pragma unroll
    for (int mt = 0; mt < 2; mt++) {
        const uint32_t row = wm0 + mt * 16 + (g & 1) * 8 + lr;
        aM[mt] = sbase + 4u * (row * 36 + (g >> 1) * 4);
    }
    #pragma unroll
    for (int np = 0; np < 2; np++) {
        const uint32_t n = wn0 + (2 * np + (g >> 1)) * 8 + lr;
        aE[np] = sbase + 4u * (9216 + n * 36 + (g & 1) * 4);
    }

    // mu pairs: 8 passes of 16 rows (split fp32 mu once)
    #pragma unroll
    for (int ps = 0; ps < 8; ps++) {
        const int row = ps * 16 + wid;
        float2 m = *(const float2*)&g_mu[(size_t)(m0 + row) * LDIM + 2 * lane];
        uint32_t l; uint32_t h = split_pack(m.x, m.y, l);
        Mh[row * 36 + lane] = h;
        Ml[row * 36 + lane] = l;
    }
    #pragma unroll
    for (int i = tid; i < KCODE; i += 512) esq_s[i] = g_esq[i];

    float best[2][2];
    int   bidx[2][2];
    #pragma unroll
    for (int i = 0; i < 2; i++)
        #pragma unroll
        for (int j = 0; j < 2; j++) { best[i][j] = 3.4e38f; bidx[i][j] = 0; }

    uint32_t uh[8], ul[8];
    for (int ct = 0; ct < 8; ct++) {
        // prefetch pre-split code tile to regs
        #pragma unroll
        for (int ps = 0; ps < 8; ps++) {
            const int row = ps * 16 + wid;
            uh[ps] = g_eth[(size_t)(ct * 128 + row) * 32 + lane];
            ul[ps] = g_etl[(size_t)(ct * 128 + row) * 32 + lane];
        }
        __syncthreads();   // prior compute done reading E (also covers mu/esq on ct=0)
        #pragma unroll
        for (int ps = 0; ps < 8; ps++) {
            const int row = ps * 16 + wid;
            Eh[row * 36 + lane] = uh[ps];
            El[row * 36 + lane] = ul[ps];
        }
        __syncthreads();

        float acc[2][4][4];
        #pragma unroll
        for (int i = 0; i < 2; i++)
            #pragma unroll
            for (int j = 0; j < 4; j++)
                #pragma unroll
                for (int e = 0; e < 4; e++) acc[i][j][e] = 0.f;

        #pragma unroll
        for (int ks = 0; ks < 4; ks++) {
            const uint32_t ko = ks * 32u;
            uint32_t ah[2][4], al[2][4], bh[4][2], bl[4][2];
            ldm_x4(ah[0], aM[0] + ko);
            ldm_x4(ah[1], aM[1] + ko);
            ldm_x4(al[0], aM[0] + ko + 18432u);
            ldm_x4(al[1], aM[1] + ko + 18432u);
            ldm_x4(&bh[0][0], aE[0] + ko);
            ldm_x4(&bh[2][0], aE[1] + ko);
            ldm_x4(&bl[0][0], aE[0] + ko + 18432u);
            ldm_x4(&bl[2][0], aE[1] + ko + 18432u);
            #pragma unroll
            for (int mt = 0; mt < 2; mt++)
                #pragma unroll
                for (int nt = 0; nt < 4; nt++) {
                    mma16(acc[mt][nt], ah[mt], bh[nt]);
                    mma16(acc[mt][nt], ah[mt], bl[nt]);
                    mma16(acc[mt][nt], al[mt], bh[nt]);
                }
        }

        // score + argmin update (ascending code order; strict < keeps first min)
        #pragma unroll
        for (int mt = 0; mt < 2; mt++)
            #pragma unroll
            for (int q = 0; q < 2; q++)
                #pragma unroll
                for (int nt = 0; nt < 4; nt++)
                    #pragma unroll
                    for (int e = 0; e < 2; e++) {
                        const int code = ct * 128 + wn0 + nt * 8 + 2 * kq + e;
                        const float sc = esq_s[code] - 2.f * acc[mt][nt][q * 2 + e];
                        if (sc < best[mt][q]) { best[mt][q] = sc; bidx[mt][q] = code; }
                    }
        __syncthreads();
    }

    // 1) reduce across the 4 lanes of each quad (same rows, different code subsets)
    #pragma unroll
    for (int mt = 0; mt < 2; mt++)
        #pragma unroll
        for (int q = 0; q < 2; q++) {
            float b = best[mt][q]; int ix = bidx[mt][q];
            #pragma unroll
            for (int s = 1; s <= 2; s <<= 1) {
                const float ob = __shfl_xor_sync(0xffffffffu, b, s);
                const int   oi = __shfl_xor_sync(0xffffffffu, ix, s);
                if (ob < b || (ob == b && oi < ix)) { b = ob; ix = oi; }
            }
            if (kq == 0) { sbest[wid][mt][q][r] = b; sidx[wid][mt][q][r] = ix; }
        }
    __syncthreads();

    // 2) merge the 4 code-quarter warps of each row group, write final index
    if (wq == 0 && kq == 0) {
        #pragma unroll
        for (int mt = 0; mt < 2; mt++)
            #pragma unroll
            for (int q = 0; q < 2; q++) {
                float b0 = sbest[wid][mt][q][r]; int i0 = sidx[wid][mt][q][r];
                #pragma unroll
                for (int w2 = 1; w2 < 4; w2++) {
                    float b1 = sbest[wid + w2][mt][q][r]; int i1 = sidx[wid + w2][mt][q][r];
                    if (b1 < b0 || (b1 == b0 && i1 < i0)) { b0 = b1; i0 = i1; }
                }
                g_idx[m0 + wm0 + mt * 16 + r + q * 8] = i0;
            }
    }
}

// ---------------- prep kernels ----------------
__global__ void wsplit2(const float* __restrict__ W, uint2* __restrict__ out,
                        int N, int K, int KU, int total)
{
    int i = blockIdx.x * 256 + threadIdx.x;
    if (i >= total) return;
    int n = i / KU, j = i - n * KU;
    int k0 = 2 * j;
    float a = (n < N && k0 < K) ? W[(size_t)n * K + k0] : 0.f;
    float b = (n < N && k0 + 1 < K) ? W[(size_t)n * K + k0 + 1] : 0.f;
    uint32_t l; uint32_t h = split_pack(a, b, l);
    out[i] = make_uint2(h, l);
}
__global__ void et_split(const float* __restrict__ embed)
{
    int i = blockIdx.x * 256 + threadIdx.x;
    if (i >= KCODE * 32) return;
    int code = i >> 5, j = i & 31;
    float a = embed[(2 * j) * KCODE + code];
    float b = embed[(2 * j + 1) * KCODE + code];
    uint32_t l; uint32_t h = split_pack(a, b, l);
    g_eth[i] = h; g_etl[i] = l;
}
__global__ void esq_kernel(const float* __restrict__ embed) {
    int k = blockIdx.x * blockDim.x + threadIdx.x;
    if (k < KCODE) {
        float s = 0.f;
        #pragma unroll 8
        for (int l = 0; l < LDIM; l++) { float e = embed[l * KCODE + k]; s += e * e; }
        g_esq[k] = s;
    }
}
__global__ void zero_counts_kernel() {
    int i = blockIdx.x * blockDim.x + threadIdx.x;
    if (i < KCODE) g_counts[i] = 0;
}

__global__ void __launch_bounds__(256) gather_loss_kernel(const float* __restrict__ embed) {
    __shared__ float ps[8];
    const int w = threadIdx.x >> 5, lane = threadIdx.x & 31;
    const int row = blockIdx.x * 8 + w;
    const int idx = g_idx[row];
    float s = 0.f;
    #pragma unroll
    for (int h = 0; h < 2; h++) {
        int l = lane + 32 * h;
        float e = embed[l * KCODE + idx];
        g_q[(size_t)row * LDIM + l] = e;
        float d = e - g_mu[(size_t)row * LDIM + l];
        s += d * d;
    }
    #pragma unroll
    for (int off = 16; off; off >>= 1) s += __shfl_down_sync(0xffffffffu, s, off);
    if (lane == 0) { ps[w] = s; atomicAdd(&g_counts[idx], 1); }
    __syncthreads();
    if (threadIdx.x == 0) {
        float t = 0.f;
        #pragma unroll
        for (int i = 0; i < 8; i++) t += ps[i];
        g_partials[blockIdx.x] = t;
    }
}

__global__ void __launch_bounds__(256) finalize_kernel(float* __restrict__ out) {
    __shared__ float red[256];
    const int t = threadIdx.x;
    float s = 0.f;
    for (int i = t; i < BB / 8; i += 256) s += g_partials[i];
    red[t] = s;
    for (int st = 128; st > 0; st >>= 1) { __syncthreads(); if (t < st) red[t] += red[t + st]; }
    __syncthreads();
    float loss = red[0] / (float)((size_t)BB * LDIM);
    __syncthreads();
    float e = 0.f;
    for (int k = t; k < KCODE; k += 256) {
        float p = (float)g_counts[k] / (float)BB;
        e += p * logf(p + 1e-10f);
    }
    red[t] = e;
    for (int st = 128; st > 0; st >>= 1) { __syncthreads(); if (t < st) red[t] += red[t + st]; }
    __syncthreads();
    if (t == 0) {
        out[(size_t)BB * FDIM] = loss;
        out[(size_t)BB * FDIM + 1] = expf(-red[0]);
    }
}

// ---------------- host launcher ----------------
#define SYM(v, s) cudaGetSymbolAddress((void**)&v, s)

extern "C" void kernel_launch(void* const* d_in, const int* in_sizes, int n_in,
                              void* d_out, int out_size)
{
    const float* x     = (const float*)d_in[0];
    const float* c     = (const float*)d_in[1];
    const float* fc1_w = (const float*)d_in[2];
    const float* fc1_b = (const float*)d_in[3];
    const float* fc2_w = (const float*)d_in[4];
    const float* fc2_b = (const float*)d_in[5];
    const float* fc3_w = (const float*)d_in[6];
    const float* fc3_b = (const float*)d_in[7];
    const float* mu_w  = (const float*)d_in[8];
    const float* mu_b  = (const float*)d_in[9];
    const float* fc4_w = (const float*)d_in[10];
    const float* fc4_b = (const float*)d_in[11];
    const float* fc5_w = (const float*)d_in[12];
    const float* fc5_b = (const float*)d_in[13];
    const float* fc6_w = (const float*)d_in[14];
    const float* fc6_b = (const float*)d_in[15];
    const float* out_w = (const float*)d_in[16];
    const float* out_b = (const float*)d_in[17];
    const float* embed = (const float*)d_in[18];
    float* out = (float*)d_out;

    float *h1, *h2, *mu, *q;
    uint2 *w1i, *w2i, *w3i, *wmi, *w4i, *w5i, *w6i, *woi;
    SYM(h1, g_h1); SYM(h2, g_h2); SYM(mu, g_mu); SYM(q, g_q);
    SYM(w1i, g_w1i); SYM(w2i, g_w2i); SYM(w3i, g_w3i); SYM(wmi, g_wmi);
    SYM(w4i, g_w4i); SYM(w5i, g_w5i); SYM(w6i, g_w6i); SYM(woi, g_woi);

    const int GEMM_SMEM = 2 * 18432 * 4;            // 147456 B
    const int VQ_SMEM   = (18432 + 1024) * 4;       // 77824 B
    cudaFuncSetAttribute(mma_gemm, cudaFuncAttributeMaxDynamicSharedMemorySize, GEMM_SMEM);
    cudaFuncSetAttribute(vq_mma,   cudaFuncAttributeMaxDynamicSharedMemorySize, VQ_SMEM);

    const dim3 blk(512);
    const dim3 g256(2, BB / 128);
    const dim3 g64(1, BB / 128);
    const dim3 g267(3, BB / 128);

    // prep: weight/codebook splits (tiny)
    wsplit2<<<(256 * KU1 + 255) / 256, 256>>>(fc1_w, w1i, 256, 534, KU1, 256 * KU1);
    wsplit2<<<(256 * KU2 + 255) / 256, 256>>>(fc2_w, w2i, 256, 256, KU2, 256 * KU2);
    wsplit2<<<(256 * KU2 + 255) / 256, 256>>>(fc3_w, w3i, 256, 256, KU2, 256 * KU2);
    wsplit2<<<(128 * KU2 + 255) / 256, 256>>>(mu_w,  wmi, 64,  256, KU2, 128 * KU2);
    wsplit2<<<(256 * KU4 + 255) / 256, 256>>>(fc4_w, w4i, 256, 331, KU4, 256 * KU4);
    wsplit2<<<(256 * KU2 + 255) / 256, 256>>>(fc5_w, w5i, 256, 256, KU2, 256 * KU2);
    wsplit2<<<(256 * KU2 + 255) / 256, 256>>>(fc6_w, w6i, 256, 256, KU2, 256 * KU2);
    wsplit2<<<(384 * KU2 + 255) / 256, 256>>>(out_w, woi, 267, 256, KU2, 384 * KU2);
    et_split<<<(KCODE * 32 + 255) / 256, 256>>>(embed);
    esq_kernel<<<4, 256>>>(embed);
    zero_counts_kernel<<<4, 256>>>();

    // encoder
    mma_gemm<<<g256, blk, GEMM_SMEM>>>(x, FDIM, c, FDIM, w1i, KU1, fc1_b, h1, HDIM, 534, 1);
    mma_gemm<<<g256, blk, GEMM_SMEM>>>(h1, HDIM, nullptr, 0, w2i, KU2, fc2_b, h2, HDIM, HDIM, 1);
    mma_gemm<<<g256, blk, GEMM_SMEM>>>(h2, HDIM, nullptr, 0, w3i, KU2, fc3_b, h1, HDIM, HDIM, 1);
    mma_gemm<<<g64,  blk, GEMM_SMEM>>>(h1, HDIM, nullptr, 0, wmi, KU2, mu_b, mu, LDIM, HDIM, 0);

    // vector quantizer
    vq_mma<<<BB / 128, 512, VQ_SMEM>>>();
    gather_loss_kernel<<<BB / 8, 256>>>(embed);

    // decoder
    mma_gemm<<<g256, blk, GEMM_SMEM>>>(q, LDIM, c, FDIM, w4i, KU4, fc4_b, h2, HDIM, 331, 1);
    mma_gemm<<<g256, blk, GEMM_SMEM>>>(h2, HDIM, nullptr, 0, w5i, KU2, fc5_b, h1, HDIM, HDIM, 1);
    mma_gemm<<<g256, blk, GEMM_SMEM>>>(h1, HDIM, nullptr, 0, w6i, KU2, fc6_b, h2, HDIM, HDIM, 1);
    mma_gemm<<<g267, blk, GEMM_SMEM>>>(h2, HDIM, nullptr, 0, woi, KU2, out_b, out, FDIM, HDIM, 0);

    // scalars
    finalize_kernel<<<1, 256>>>(out);
}

// round 12
// speedup vs baseline: 1.0719x; 1.0237x over previous
#include <cuda_runtime.h>
#include <cstdint>
#include <math.h>

#define BB 65536
#define FDIM 267
#define HDIM 256
#define LDIM 64
#define KCODE 1024

// pair strides (uint2 per 2 K-elems), K padded to 32-pair (64-elem) chunk multiples
#define KU1 288   // fc1: K=534 -> 9 chunks (fp32 path)
#define KU2 128   // K=256 -> 4 chunks
#define KU4 192   // fc4: K=331 -> 6 chunks (fp32 path)

// ---------------- scratch (device globals) ----------------
__device__ uint2 g_h1p[BB * KU2];
__device__ uint2 g_h2p[BB * KU2];
__device__ float g_mu[BB * LDIM];
__device__ float g_q[BB * LDIM];
__device__ int   g_idx[BB];
__device__ float g_esq[KCODE];
__device__ int   g_counts[KCODE];
__device__ float g_partials[BB / 8];
__device__ uint32_t g_eth[KCODE * 32], g_etl[KCODE * 32];  // codebook pairs [code][l/2]
__device__ uint2 g_w1i[256 * KU1];
__device__ uint2 g_w2i[256 * KU2];
__device__ uint2 g_w3i[256 * KU2];
__device__ uint2 g_wmi[128 * KU2];
__device__ uint2 g_w4i[256 * KU4];
__device__ uint2 g_w5i[256 * KU2];
__device__ uint2 g_w6i[256 * KU2];
__device__ uint2 g_woi[384 * KU2];

// ---------------- helpers ----------------
__device__ __forceinline__ float hi32(float a) {
    return __uint_as_float(__float_as_uint(a) & 0xFFFFE000u);
}
__device__ __forceinline__ uint32_t packh(float x, float y) {
    uint32_t d;
    asm("cvt.rn.f16x2.f32 %0, %1, %2;" : "=r"(d) : "f"(y), "f"(x));
    return d;
}
__device__ __forceinline__ uint32_t split_pack(float a, float b, uint32_t& lo) {
    float ha = hi32(a), hb = hi32(b);
    lo = packh(a - ha, b - hb);
    return packh(ha, hb);
}
__device__ __forceinline__ uint32_t smem_u32(const void* p) {
    uint32_t a;
    asm("{ .reg .u64 t; cvta.to.shared.u64 t, %1; cvt.u32.u64 %0, t; }" : "=r"(a) : "l"(p));
    return a;
}
__device__ __forceinline__ void ldm_x4(uint32_t* d, uint32_t a) {
    asm volatile("ldmatrix.sync.aligned.m8n8.x4.shared.b16 {%0,%1,%2,%3}, [%4];"
        : "=r"(d[0]), "=r"(d[1]), "=r"(d[2]), "=r"(d[3]) : "r"(a));
}
__device__ __forceinline__ void mma16(float* d, const uint32_t* a, const uint32_t* b) {
    asm volatile(
        "mma.sync.aligned.m16n8k16.row.col.f32.f16.f16.f32 "
        "{%0,%1,%2,%3},{%4,%5,%6,%7},{%8,%9},{%0,%1,%2,%3};"
        : "+f"(d[0]), "+f"(d[1]), "+f"(d[2]), "+f"(d[3])
        : "r"(a[0]), "r"(a[1]), "r"(a[2]), "r"(a[3]), "r"(b[0]), "r"(b[1]));
}

// ---------------- fp16x3 HMMA GEMM, template on A-source ----------------
// C = act(A * W^T + b). 128x128 CTA tile, BK=64, 16 warps (4m x 4n), warp tile 32x32.
// PAIRS_A=true : A = pre-split uint2 pair array Ap (K exact multiple of 64).
// PAIRS_A=false: A = fp32 concat [A0|A1], split on the fly (guarded).
// B: pre-split interleaved uint2 pairs (padded).
// Output: fp32 Cf and/or pair array Cp (stride NUp pairs).
// smem u32 per buf: Ahi[128][36] | Alo | Bhi | Blo = 18432; 2 bufs = 147456 B.
template <bool PAIRS_A>
__global__ void __launch_bounds__(512, 1) mma_gemm(
    const float* __restrict__ A0, int W0,
    const float* __restrict__ A1, int W1,
    const uint2* __restrict__ Ap, int KUa,
    const uint2* __restrict__ Wt, int KUb,
    const float* __restrict__ bias,
    float* __restrict__ Cf, uint2* __restrict__ Cp, int NUp,
    int N, int K, int relu)
{
    extern __shared__ uint32_t smu[];

    const int tid = threadIdx.x, lane = tid & 31, wid = tid >> 5;
    const int m0 = blockIdx.y * 128, bn = blockIdx.x * 128;
    const int wm0 = (wid >> 2) * 32, wn0 = (wid & 3) * 32;
    const int r = lane >> 2, kq = lane & 3;
    const int NC = (K + 63) >> 6;
    const int prow = tid >> 4;     // 0..31 loader row
    const int pj   = tid & 15;     // segment index (4 fp32 / 2 pair-u32 wide)

    // ldmatrix lane addresses (buffer 0); row stride 36 u32 (16B-aligned, conflict-free)
    const uint32_t sbase = smem_u32(smu);
    const int g = lane >> 3, lr = lane & 7;
    uint32_t aA[2], aB[2];
    #pragma unroll
    for (int mt = 0; mt < 2; mt++) {
        const uint32_t row = wm0 + mt * 16 + (g & 1) * 8 + lr;
        aA[mt] = sbase + 4u * (row * 36 + (g >> 1) * 4);
    }
    #pragma unroll
    for (int np = 0; np < 2; np++) {
        const uint32_t n = wn0 + (2 * np + (g >> 1)) * 8 + lr;
        aB[np] = sbase + 4u * (9216 + n * 36 + (g & 1) * 4);
    }

    float acc[2][4][4];
    #pragma unroll
    for (int i = 0; i < 2; i++)
        #pragma unroll
        for (int j = 0; j < 4; j++)
            #pragma unroll
            for (int e = 0; e < 4; e++) acc[i][j][e] = 0.f;

    float4 a4[4];
    uint4  aU[4];
    uint4  b4[4];

    auto prefetch = [&](int c) {
        const size_t bo = (size_t)c * 32 + 2 * pj;
        #pragma unroll
        for (int p = 0; p < 4; p++) {
            const int row = p * 32 + prow;
            if (PAIRS_A) {
                aU[p] = *(const uint4*)&Ap[(size_t)(m0 + row) * KUa + bo];
            } else {
                const int kg0 = c * 64 + 4 * pj;
                float v[4];
                #pragma unroll
                for (int e = 0; e < 4; e++) {
                    const int kg = kg0 + e;
                    float t = 0.f;
                    if (kg < K)
                        t = (kg < W0) ? A0[(size_t)(m0 + row) * W0 + kg]
                                      : A1[(size_t)(m0 + row) * W1 + (kg - W0)];
                    v[e] = t;
                }
                a4[p] = make_float4(v[0], v[1], v[2], v[3]);
            }
            b4[p] = *(const uint4*)&Wt[(size_t)(bn + row) * KUb + bo];
        }
    };
    auto store = [&](int b) {
        uint32_t* base = smu + b * 18432;
        #pragma unroll
        for (int p = 0; p < 4; p++) {
            const int o = (p * 32 + prow) * 36 + 2 * pj;
            if (PAIRS_A) {
                base[o]            = aU[p].x;
                base[o + 1]        = aU[p].z;
                base[4608 + o]     = aU[p].y;
                base[4608 + o + 1] = aU[p].w;
            } else {
                const float h0 = hi32(a4[p].x), h1 = hi32(a4[p].y);
                const float h2 = hi32(a4[p].z), h3 = hi32(a4[p].w);
                base[o]            = packh(h0, h1);
                base[o + 1]        = packh(h2, h3);
                base[4608 + o]     = packh(a4[p].x - h0, a4[p].y - h1);
                base[4608 + o + 1] = packh(a4[p].z - h2, a4[p].w - h3);
            }
            base[9216 + o]      = b4[p].x;
            base[9216 + o + 1]  = b4[p].z;
            base[13824 + o]     = b4[p].y;
            base[13824 + o + 1] = b4[p].w;
        }
    };
    auto compute = [&]() {
        #pragma unroll
        for (int ks = 0; ks < 4; ks++) {
            const uint32_t ko = ks * 32u;      // 8 u32 per ks step
            uint32_t ah[2][4], al[2][4], bh[4][2], bl[4][2];
            ldm_x4(ah[0], aA[0] + ko);
            ldm_x4(ah[1], aA[1] + ko);
            ldm_x4(al[0], aA[0] + ko + 18432u);
            ldm_x4(al[1], aA[1] + ko + 18432u);
            ldm_x4(&bh[0][0], aB[0] + ko);
            ldm_x4(&bh[2][0], aB[1] + ko);
            ldm_x4(&bl[0][0], aB[0] + ko + 18432u);
            ldm_x4(&bl[2][0], aB[1] + ko + 18432u);
            #pragma unroll
            for (int mt = 0; mt < 2; mt++)
                #pragma unroll
                for (int nt = 0; nt < 4; nt++) {
                    mma16(acc[mt][nt], ah[mt], bh[nt]);
                    mma16(acc[mt][nt], ah[mt], bl[nt]);
                    mma16(acc[mt][nt], al[mt], bh[nt]);
                }
        }
    };

    prefetch(0); store(0); __syncthreads();
    int32_t dshift = 73728;
    for (int c = 0; c < NC; c++) {
        if (c + 1 < NC) prefetch(c + 1);
        compute();
        if (c + 1 < NC) store((c + 1) & 1);
        __syncthreads();
        if (c + 1 < NC) {
            aA[0] += dshift; aA[1] += dshift;
            aB[0] += dshift; aB[1] += dshift;
            dshift = -dshift;
        }
    }

    // epilogue: bias + relu; optional fp32 / pair outputs
    const bool evenN = (N & 1) == 0;
    #pragma unroll
    for (int mt = 0; mt < 2; mt++) {
        #pragma unroll
        for (int q = 0; q < 2; q++) {
            const int row = m0 + wm0 + mt * 16 + q * 8 + r;
            #pragma unroll
            for (int nt = 0; nt < 4; nt++) {
                const int n = bn + wn0 + nt * 8 + 2 * kq;
                float v0 = acc[mt][nt][q * 2 + 0];
                float v1 = acc[mt][nt][q * 2 + 1];
                if (n + 1 < N) {
                    float o0 = v0 + bias[n];
                    float o1 = v1 + bias[n + 1];
                    if (relu) { o0 = fmaxf(o0, 0.f); o1 = fmaxf(o1, 0.f); }
                    if (Cp) {
                        uint32_t l; uint32_t h = split_pack(o0, o1, l);
                        Cp[(size_t)row * NUp + (n >> 1)] = make_uint2(h, l);
                    }
                    if (Cf) {
                        if (evenN) {
                            float2 p; p.x = o0; p.y = o1;
                            *(float2*)&Cf[(size_t)row * N + n] = p;
                        } else {
                            Cf[(size_t)row * N + n] = o0;
                            Cf[(size_t)row * N + n + 1] = o1;
                        }
                    }
                } else if (n < N && Cf) {
                    float o0 = v0 + bias[n];
                    if (relu) o0 = fmaxf(o0, 0.f);
                    Cf[(size_t)row * N + n] = o0;
                }
            }
        }
    }
}

// ---------------- VQ argmin via fp16x3 HMMA + ldmatrix, 512 threads ----------------
// 128 rows/CTA, 8 code-tiles of 128, K=64. 16 warps: 4 row-groups x 4 code-quarters.
// score = esq[k] - 2*mu.e_k ; ties -> lowest index.
__global__ void __launch_bounds__(512, 1) vq_mma()
{
    extern __shared__ uint32_t smv[];
    uint32_t* Mh = smv;             // [128][36]
    uint32_t* Ml = smv + 4608;
    uint32_t* Eh = smv + 9216;
    uint32_t* El = smv + 13824;
    float* esq_s = (float*)(smv + 18432);

    __shared__ float sbest[16][2][2][8];
    __shared__ int   sidx[16][2][2][8];

    const int tid = threadIdx.x, lane = tid & 31, wid = tid >> 5;
    const int m0 = blockIdx.x * 128;
    const int wm0 = (wid >> 2) * 32;
    const int wq  = wid & 3;
    const int wn0 = wq * 32;
    const int r = lane >> 2, kq = lane & 3;

    const uint32_t sbase = smem_u32(smv);
    const int g = lane >> 3, lr = lane & 7;
    uint32_t aM[2], aE[2];
    #pragma unroll
    for (int mt = 0; mt < 2; mt++) {
        const uint32_t row = wm0 + mt * 16 + (g & 1) * 8 + lr;
        aM[mt] = sbase + 4u * (row * 36 + (g >> 1) * 4);
    }
    #pragma unroll
    for (int np = 0; np < 2; np++) {
        const uint32_t n = wn0 + (2 * np + (g >> 1)) * 8 + lr;
        aE[np] = sbase + 4u * (9216 + n * 36 + (g & 1) * 4);
    }

    // mu pairs: 8 passes of 16 rows (split fp32 mu once)
    #pragma unroll
    for (int ps = 0; ps < 8; ps++) {
        const int row = ps * 16 + wid;
        float2 m = *(const float2*)&g_mu[(size_t)(m0 + row) * LDIM + 2 * lane];
        uint32_t l; uint32_t h = split_pack(m.x, m.y, l);
        Mh[row * 36 + lane] = h;
        Ml[row * 36 + lane] = l;
    }
    #pragma unroll
    for (int i = tid; i < KCODE; i += 512) esq_s[i] = g_esq[i];

    float best[2][2];
    int   bidx[2][2];
    #pragma unroll
    for (int i = 0; i < 2; i++)
        #pragma unroll
        for (int j = 0; j < 2; j++) { best[i][j] = 3.4e38f; bidx[i][j] = 0; }

    uint32_t uh[8], ul[8];
    for (int ct = 0; ct < 8; ct++) {
        // prefetch pre-split code tile to regs
        #pragma unroll
        for (int ps = 0; ps < 8; ps++) {
            const int row = ps * 16 + wid;
            uh[ps] = g_eth[(size_t)(ct * 128 + row) * 32 + lane];
            ul[ps] = g_etl[(size_t)(ct * 128 + row) * 32 + lane];
        }
        __syncthreads();   // prior compute done reading E (also covers mu/esq on ct=0)
        #pragma unroll
        for (int ps = 0; ps < 8; ps++) {
            const int row = ps * 16 + wid;
            Eh[row * 36 + lane] = uh[ps];
            El[row * 36 + lane] = ul[ps];
        }
        __syncthreads();

        float acc[2][4][4];
        #pragma unroll
        for (int i = 0; i < 2; i++)
            #pragma unroll
            for (int j = 0; j < 4; j++)
                #pragma unroll
                for (int e = 0; e < 4; e++) acc[i][j][e] = 0.f;

        #pragma unroll
        for (int ks = 0; ks < 4; ks++) {
            const uint32_t ko = ks * 32u;
            uint32_t ah[2][4], al[2][4], bh[4][2], bl[4][2];
            ldm_x4(ah[0], aM[0] + ko);
            ldm_x4(ah[1], aM[1] + ko);
            ldm_x4(al[0], aM[0] + ko + 18432u);
            ldm_x4(al[1], aM[1] + ko + 18432u);
            ldm_x4(&bh[0][0], aE[0] + ko);
            ldm_x4(&bh[2][0], aE[1] + ko);
            ldm_x4(&bl[0][0], aE[0] + ko + 18432u);
            ldm_x4(&bl[2][0], aE[1] + ko + 18432u);
            #pragma unroll
            for (int mt = 0; mt < 2; mt++)
                #pragma unroll
                for (int nt = 0; nt < 4; nt++) {
                    mma16(acc[mt][nt], ah[mt], bh[nt]);
                    mma16(acc[mt][nt], ah[mt], bl[nt]);
                    mma16(acc[mt][nt], al[mt], bh[nt]);
                }
        }

        // score + argmin update (ascending code order; strict < keeps first min)
        #pragma unroll
        for (int mt = 0; mt < 2; mt++)
            #pragma unroll
            for (int q = 0; q < 2; q++)
                #pragma unroll
                for (int nt = 0; nt < 4; nt++)
                    #pragma unroll
                    for (int e = 0; e < 2; e++) {
                        const int code = ct * 128 + wn0 + nt * 8 + 2 * kq + e;
                        const float sc = esq_s[code] - 2.f * acc[mt][nt][q * 2 + e];
                        if (sc < best[mt][q]) { best[mt][q] = sc; bidx[mt][q] = code; }
                    }
        __syncthreads();
    }

    // 1) reduce across the 4 lanes of each quad (same rows, different code subsets)
    #pragma unroll
    for (int mt = 0; mt < 2; mt++)
        #pragma unroll
        for (int q = 0; q < 2; q++) {
            float b = best[mt][q]; int ix = bidx[mt][q];
            #pragma unroll
            for (int s = 1; s <= 2; s <<= 1) {
                const float ob = __shfl_xor_sync(0xffffffffu, b, s);
                const int   oi = __shfl_xor_sync(0xffffffffu, ix, s);
                if (ob < b || (ob == b && oi < ix)) { b = ob; ix = oi; }
            }
            if (kq == 0) { sbest[wid][mt][q][r] = b; sidx[wid][mt][q][r] = ix; }
        }
    __syncthreads();

    // 2) merge the 4 code-quarter warps of each row group, write final index
    if (wq == 0 && kq == 0) {
        #pragma unroll
        for (int mt = 0; mt < 2; mt++)
            #pragma unroll
            for (int q = 0; q < 2; q++) {
                float b0 = sbest[wid][mt][q][r]; int i0 = sidx[wid][mt][q][r];
                #pragma unroll
                for (int w2 = 1; w2 < 4; w2++) {
                    float b1 = sbest[wid + w2][mt][q][r]; int i1 = sidx[wid + w2][mt][q][r];
                    if (b1 < b0 || (b1 == b0 && i1 < i0)) { b0 = b1; i0 = i1; }
                }
                g_idx[m0 + wm0 + mt * 16 + r + q * 8] = i0;
            }
    }
}

// ---------------- prep kernels ----------------
__global__ void wsplit2(const float* __restrict__ W, uint2* __restrict__ out,
                        int N, int K, int KU, int total)
{
    int i = blockIdx.x * 256 + threadIdx.x;
    if (i >= total) return;
    int n = i / KU, j = i - n * KU;
    int k0 = 2 * j;
    float a = (n < N && k0 < K) ? W[(size_t)n * K + k0] : 0.f;
    float b = (n < N && k0 + 1 < K) ? W[(size_t)n * K + k0 + 1] : 0.f;
    uint32_t l; uint32_t h = split_pack(a, b, l);
    out[i] = make_uint2(h, l);
}
__global__ void et_split(const float* __restrict__ embed)
{
    int i = blockIdx.x * 256 + threadIdx.x;
    if (i >= KCODE * 32) return;
    int code = i >> 5, j = i & 31;
    float a = embed[(2 * j) * KCODE + code];
    float b = embed[(2 * j + 1) * KCODE + code];
    uint32_t l; uint32_t h = split_pack(a, b, l);
    g_eth[i] = h; g_etl[i] = l;
}
__global__ void esq_kernel(const float* __restrict__ embed) {
    int k = blockIdx.x * blockDim.x + threadIdx.x;
    if (k < KCODE) {
        float s = 0.f;
        #pragma unroll 8
        for (int l = 0; l < LDIM; l++) { float e = embed[l * KCODE + k]; s += e * e; }
        g_esq[k] = s;
    }
}
__global__ void zero_counts_kernel() {
    int i = blockIdx.x * blockDim.x + threadIdx.x;
    if (i < KCODE) g_counts[i] = 0;
}

__global__ void __launch_bounds__(256) gather_loss_kernel(const float* __restrict__ embed) {
    __shared__ float ps[8];
    const int w = threadIdx.x >> 5, lane = threadIdx.x & 31;
    const int row = blockIdx.x * 8 + w;
    const int idx = g_idx[row];
    float s = 0.f;
    #pragma unroll
    for (int h = 0; h < 2; h++) {
        int l = lane + 32 * h;
        float e = embed[l * KCODE + idx];
        g_q[(size_t)row * LDIM + l] = e;
        float d = e - g_mu[(size_t)row * LDIM + l];
        s += d * d;
    }
    #pragma unroll
    for (int off = 16; off; off >>= 1) s += __shfl_down_sync(0xffffffffu, s, off);
    if (lane == 0) { ps[w] = s; atomicAdd(&g_counts[idx], 1); }
    __syncthreads();
    if (threadIdx.x == 0) {
        float t = 0.f;
        #pragma unroll
        for (int i = 0; i < 8; i++) t += ps[i];
        g_partials[blockIdx.x] = t;
    }
}

__global__ void __launch_bounds__(256) finalize_kernel(float* __restrict__ out) {
    __shared__ float red[256];
    const int t = threadIdx.x;
    float s = 0.f;
    for (int i = t; i < BB / 8; i += 256) s += g_partials[i];
    red[t] = s;
    for (int st = 128; st > 0; st >>= 1) { __syncthreads(); if (t < st) red[t] += red[t + st]; }
    __syncthreads();
    float loss = red[0] / (float)((size_t)BB * LDIM);
    __syncthreads();
    float e = 0.f;
    for (int k = t; k < KCODE; k += 256) {
        float p = (float)g_counts[k] / (float)BB;
        e += p * logf(p + 1e-10f);
    }
    red[t] = e;
    for (int st = 128; st > 0; st >>= 1) { __syncthreads(); if (t < st) red[t] += red[t + st]; }
    __syncthreads();
    if (t == 0) {
        out[(size_t)BB * FDIM] = loss;
        out[(size_t)BB * FDIM + 1] = expf(-red[0]);
    }
}

// ---------------- host launcher ----------------
#define SYM(v, s) cudaGetSymbolAddress((void**)&v, s)

extern "C" void kernel_launch(void* const* d_in, const int* in_sizes, int n_in,
                              void* d_out, int out_size)
{
    const float* x     = (const float*)d_in[0];
    const float* c     = (const float*)d_in[1];
    const float* fc1_w = (const float*)d_in[2];
    const float* fc1_b = (const float*)d_in[3];
    const float* fc2_w = (const float*)d_in[4];
    const float* fc2_b = (const float*)d_in[5];
    const float* fc3_w = (const float*)d_in[6];
    const float* fc3_b = (const float*)d_in[7];
    const float* mu_w  = (const float*)d_in[8];
    const float* mu_b  = (const float*)d_in[9];
    const float* fc4_w = (const float*)d_in[10];
    const float* fc4_b = (const float*)d_in[11];
    const float* fc5_w = (const float*)d_in[12];
    const float* fc5_b = (const float*)d_in[13];
    const float* fc6_w = (const float*)d_in[14];
    const float* fc6_b = (const float*)d_in[15];
    const float* out_w = (const float*)d_in[16];
    const float* out_b = (const float*)d_in[17];
    const float* embed = (const float*)d_in[18];
    float* out = (float*)d_out;

    float *mu, *q;
    uint2 *h1p, *h2p;
    uint2 *w1i, *w2i, *w3i, *wmi, *w4i, *w5i, *w6i, *woi;
    SYM(mu, g_mu); SYM(q, g_q);
    SYM(h1p, g_h1p); SYM(h2p, g_h2p);
    SYM(w1i, g_w1i); SYM(w2i, g_w2i); SYM(w3i, g_w3i); SYM(wmi, g_wmi);
    SYM(w4i, g_w4i); SYM(w5i, g_w5i); SYM(w6i, g_w6i); SYM(woi, g_woi);

    const int GEMM_SMEM = 2 * 18432 * 4;            // 147456 B
    const int VQ_SMEM   = (18432 + 1024) * 4;       // 77824 B
    cudaFuncSetAttribute(mma_gemm<false>, cudaFuncAttributeMaxDynamicSharedMemorySize, GEMM_SMEM);
    cudaFuncSetAttribute(mma_gemm<true>,  cudaFuncAttributeMaxDynamicSharedMemorySize, GEMM_SMEM);
    cudaFuncSetAttribute(vq_mma, cudaFuncAttributeMaxDynamicSharedMemorySize, VQ_SMEM);

    const dim3 blk(512);
    const dim3 g256(2, BB / 128);
    const dim3 g64(1, BB / 128);
    const dim3 g267(3, BB / 128);

    // prep: weight/codebook splits (tiny)
    wsplit2<<<(256 * KU1 + 255) / 256, 256>>>(fc1_w, w1i, 256, 534, KU1, 256 * KU1);
    wsplit2<<<(256 * KU2 + 255) / 256, 256>>>(fc2_w, w2i, 256, 256, KU2, 256 * KU2);
    wsplit2<<<(256 * KU2 + 255) / 256, 256>>>(fc3_w, w3i, 256, 256, KU2, 256 * KU2);
    wsplit2<<<(128 * KU2 + 255) / 256, 256>>>(mu_w,  wmi, 64,  256, KU2, 128 * KU2);
    wsplit2<<<(256 * KU4 + 255) / 256, 256>>>(fc4_w, w4i, 256, 331, KU4, 256 * KU4);
    wsplit2<<<(256 * KU2 + 255) / 256, 256>>>(fc5_w, w5i, 256, 256, KU2, 256 * KU2);
    wsplit2<<<(256 * KU2 + 255) / 256, 256>>>(fc6_w, w6i, 256, 256, KU2, 256 * KU2);
    wsplit2<<<(384 * KU2 + 255) / 256, 256>>>(out_w, woi, 267, 256, KU2, 384 * KU2);
    et_split<<<(KCODE * 32 + 255) / 256, 256>>>(embed);
    esq_kernel<<<4, 256>>>(embed);
    zero_counts_kernel<<<4, 256>>>();

    // encoder
    mma_gemm<false><<<g256, blk, GEMM_SMEM>>>(x, FDIM, c, FDIM, nullptr, 0, w1i, KU1, fc1_b,
                                              nullptr, h1p, KU2, HDIM, 534, 1);
    mma_gemm<true><<<g256, blk, GEMM_SMEM>>>(nullptr, 0, nullptr, 0, h1p, KU2, w2i, KU2, fc2_b,
                                             nullptr, h2p, KU2, HDIM, HDIM, 1);
    mma_gemm<true><<<g256, blk, GEMM_SMEM>>>(nullptr, 0, nullptr, 0, h2p, KU2, w3i, KU2, fc3_b,
                                             nullptr, h1p, KU2, HDIM, HDIM, 1);
    mma_gemm<true><<<g64, blk, GEMM_SMEM>>>(nullptr, 0, nullptr, 0, h1p, KU2, wmi, KU2, mu_b,
                                            mu, nullptr, 0, LDIM, HDIM, 0);

    // vector quantizer
    vq_mma<<<BB / 128, 512, VQ_SMEM>>>();
    gather_loss_kernel<<<BB / 8, 256>>>(embed);

    // decoder
    mma_gemm<false><<<g256, blk, GEMM_SMEM>>>(q, LDIM, c, FDIM, nullptr, 0, w4i, KU4, fc4_b,
                                              nullptr, h2p, KU2, HDIM, 331, 1);
    mma_gemm<true><<<g256, blk, GEMM_SMEM>>>(nullptr, 0, nullptr, 0, h2p, KU2, w5i, KU2, fc5_b,
                                             nullptr, h1p, KU2, HDIM, HDIM, 1);
    mma_gemm<true><<<g256, blk, GEMM_SMEM>>>(nullptr, 0, nullptr, 0, h1p, KU2, w6i, KU2, fc6_b,
                                             nullptr, h2p, KU2, HDIM, HDIM, 1);
    mma_gemm<true><<<g267, blk, GEMM_SMEM>>>(nullptr, 0, nullptr, 0, h2p, KU2, woi, KU2, out_b,
                                             out, nullptr, 0, FDIM, HDIM, 0);

    // scalars
    finalize_kernel<<<1, 256>>>(out);
}

// round 13
// speedup vs baseline: 1.0979x; 1.0242x over previous
#include <cuda_runtime.h>
#include <cuda_fp16.h>
#include <cstdint>
#include <math.h>

#define BB 65536
#define FDIM 267
#define HDIM 256
#define LDIM 64
#define KCODE 1024

// pair strides (uint2 per 2 K-elems), K padded to 32-pair (64-elem) chunk multiples
#define KU1 288   // fc1: K=534 -> 9 chunks (fp32 path)
#define KU2 128   // K=256 -> 4 chunks
#define KU4 192   // fc4: K=331 -> 6 chunks (fp32 path)

// ---------------- scratch (device globals) ----------------
__device__ uint2 g_h1p[BB * KU2];
__device__ uint2 g_h2p[BB * KU2];
__device__ float g_q[BB * LDIM];
__device__ float g_esq[KCODE];
__device__ int   g_counts[KCODE];
__device__ float g_partials[512];
__device__ uint32_t g_eth[KCODE * 32], g_etl[KCODE * 32];  // codebook pairs [code][l/2]
__device__ uint2 g_w1i[256 * KU1];
__device__ uint2 g_w2i[256 * KU2];
__device__ uint2 g_w3i[256 * KU2];
__device__ uint2 g_wmi[128 * KU2];
__device__ uint2 g_w4i[256 * KU4];
__device__ uint2 g_w5i[256 * KU2];
__device__ uint2 g_w6i[256 * KU2];
__device__ uint2 g_woi[384 * KU2];

// ---------------- helpers ----------------
__device__ __forceinline__ float hi32(float a) {
    return __uint_as_float(__float_as_uint(a) & 0xFFFFE000u);
}
__device__ __forceinline__ uint32_t packh(float x, float y) {
    uint32_t d;
    asm("cvt.rn.f16x2.f32 %0, %1, %2;" : "=r"(d) : "f"(y), "f"(x));
    return d;
}
__device__ __forceinline__ uint32_t split_pack(float a, float b, uint32_t& lo) {
    float ha = hi32(a), hb = hi32(b);
    lo = packh(a - ha, b - hb);
    return packh(ha, hb);
}
__device__ __forceinline__ uint32_t smem_u32(const void* p) {
    uint32_t a;
    asm("{ .reg .u64 t; cvta.to.shared.u64 t, %1; cvt.u32.u64 %0, t; }" : "=r"(a) : "l"(p));
    return a;
}
__device__ __forceinline__ void ldm_x4(uint32_t* d, uint32_t a) {
    asm volatile("ldmatrix.sync.aligned.m8n8.x4.shared.b16 {%0,%1,%2,%3}, [%4];"
        : "=r"(d[0]), "=r"(d[1]), "=r"(d[2]), "=r"(d[3]) : "r"(a));
}
__device__ __forceinline__ void mma16(float* d, const uint32_t* a, const uint32_t* b) {
    asm volatile(
        "mma.sync.aligned.m16n8k16.row.col.f32.f16.f16.f32 "
        "{%0,%1,%2,%3},{%4,%5,%6,%7},{%8,%9},{%0,%1,%2,%3};"
        : "+f"(d[0]), "+f"(d[1]), "+f"(d[2]), "+f"(d[3])
        : "r"(a[0]), "r"(a[1]), "r"(a[2]), "r"(a[3]), "r"(b[0]), "r"(b[1]));
}

// ---------------- fp16x3 HMMA GEMM, template on A-source (proven R12) ----------------
template <bool PAIRS_A>
__global__ void __launch_bounds__(512, 1) mma_gemm(
    const float* __restrict__ A0, int W0,
    const float* __restrict__ A1, int W1,
    const uint2* __restrict__ Ap, int KUa,
    const uint2* __restrict__ Wt, int KUb,
    const float* __restrict__ bias,
    float* __restrict__ Cf, uint2* __restrict__ Cp, int NUp,
    int N, int K, int relu)
{
    extern __shared__ uint32_t smu[];

    const int tid = threadIdx.x, lane = tid & 31, wid = tid >> 5;
    const int m0 = blockIdx.y * 128, bn = blockIdx.x * 128;
    const int wm0 = (wid >> 2) * 32, wn0 = (wid & 3) * 32;
    const int r = lane >> 2, kq = lane & 3;
    const int NC = (K + 63) >> 6;
    const int prow = tid >> 4;
    const int pj   = tid & 15;

    const uint32_t sbase = smem_u32(smu);
    const int g = lane >> 3, lr = lane & 7;
    uint32_t aA[2], aB[2];
    #pragma unroll
    for (int mt = 0; mt < 2; mt++) {
        const uint32_t row = wm0 + mt * 16 + (g & 1) * 8 + lr;
        aA[mt] = sbase + 4u * (row * 36 + (g >> 1) * 4);
    }
    #pragma unroll
    for (int np = 0; np < 2; np++) {
        const uint32_t n = wn0 + (2 * np + (g >> 1)) * 8 + lr;
        aB[np] = sbase + 4u * (9216 + n * 36 + (g & 1) * 4);
    }

    float acc[2][4][4];
    #pragma unroll
    for (int i = 0; i < 2; i++)
        #pragma unroll
        for (int j = 0; j < 4; j++)
            #pragma unroll
            for (int e = 0; e < 4; e++) acc[i][j][e] = 0.f;

    float4 a4[4];
    uint4  aU[4];
    uint4  b4[4];

    auto prefetch = [&](int c) {
        const size_t bo = (size_t)c * 32 + 2 * pj;
        #pragma unroll
        for (int p = 0; p < 4; p++) {
            const int row = p * 32 + prow;
            if (PAIRS_A) {
                aU[p] = *(const uint4*)&Ap[(size_t)(m0 + row) * KUa + bo];
            } else {
                const int kg0 = c * 64 + 4 * pj;
                float v[4];
                #pragma unroll
                for (int e = 0; e < 4; e++) {
                    const int kg = kg0 + e;
                    float t = 0.f;
                    if (kg < K)
                        t = (kg < W0) ? A0[(size_t)(m0 + row) * W0 + kg]
                                      : A1[(size_t)(m0 + row) * W1 + (kg - W0)];
                    v[e] = t;
                }
                a4[p] = make_float4(v[0], v[1], v[2], v[3]);
            }
            b4[p] = *(const uint4*)&Wt[(size_t)(bn + row) * KUb + bo];
        }
    };
    auto store = [&](int b) {
        uint32_t* base = smu + b * 18432;
        #pragma unroll
        for (int p = 0; p < 4; p++) {
            const int o = (p * 32 + prow) * 36 + 2 * pj;
            if (PAIRS_A) {
                base[o]            = aU[p].x;
                base[o + 1]        = aU[p].z;
                base[4608 + o]     = aU[p].y;
                base[4608 + o + 1] = aU[p].w;
            } else {
                const float h0 = hi32(a4[p].x), h1 = hi32(a4[p].y);
                const float h2 = hi32(a4[p].z), h3 = hi32(a4[p].w);
                base[o]            = packh(h0, h1);
                base[o + 1]        = packh(h2, h3);
                base[4608 + o]     = packh(a4[p].x - h0, a4[p].y - h1);
                base[4608 + o + 1] = packh(a4[p].z - h2, a4[p].w - h3);
            }
            base[9216 + o]      = b4[p].x;
            base[9216 + o + 1]  = b4[p].z;
            base[13824 + o]     = b4[p].y;
            base[13824 + o + 1] = b4[p].w;
        }
    };
    auto compute = [&]() {
        #pragma unroll
        for (int ks = 0; ks < 4; ks++) {
            const uint32_t ko = ks * 32u;
            uint32_t ah[2][4], al[2][4], bh[4][2], bl[4][2];
            ldm_x4(ah[0], aA[0] + ko);
            ldm_x4(ah[1], aA[1] + ko);
            ldm_x4(al[0], aA[0] + ko + 18432u);
            ldm_x4(al[1], aA[1] + ko + 18432u);
            ldm_x4(&bh[0][0], aB[0] + ko);
            ldm_x4(&bh[2][0], aB[1] + ko);
            ldm_x4(&bl[0][0], aB[0] + ko + 18432u);
            ldm_x4(&bl[2][0], aB[1] + ko + 18432u);
            #pragma unroll
            for (int mt = 0; mt < 2; mt++)
                #pragma unroll
                for (int nt = 0; nt < 4; nt++) {
                    mma16(acc[mt][nt], ah[mt], bh[nt]);
                    mma16(acc[mt][nt], ah[mt], bl[nt]);
                    mma16(acc[mt][nt], al[mt], bh[nt]);
                }
        }
    };

    prefetch(0); store(0); __syncthreads();
    int32_t dshift = 73728;
    for (int c = 0; c < NC; c++) {
        if (c + 1 < NC) prefetch(c + 1);
        compute();
        if (c + 1 < NC) store((c + 1) & 1);
        __syncthreads();
        if (c + 1 < NC) {
            aA[0] += dshift; aA[1] += dshift;
            aB[0] += dshift; aB[1] += dshift;
            dshift = -dshift;
        }
    }

    const bool evenN = (N & 1) == 0;
    #pragma unroll
    for (int mt = 0; mt < 2; mt++) {
        #pragma unroll
        for (int q = 0; q < 2; q++) {
            const int row = m0 + wm0 + mt * 16 + q * 8 + r;
            #pragma unroll
            for (int nt = 0; nt < 4; nt++) {
                const int n = bn + wn0 + nt * 8 + 2 * kq;
                float v0 = acc[mt][nt][q * 2 + 0];
                float v1 = acc[mt][nt][q * 2 + 1];
                if (n + 1 < N) {
                    float o0 = v0 + bias[n];
                    float o1 = v1 + bias[n + 1];
                    if (relu) { o0 = fmaxf(o0, 0.f); o1 = fmaxf(o1, 0.f); }
                    if (Cp) {
                        uint32_t l; uint32_t h = split_pack(o0, o1, l);
                        Cp[(size_t)row * NUp + (n >> 1)] = make_uint2(h, l);
                    }
                    if (Cf) {
                        if (evenN) {
                            float2 p; p.x = o0; p.y = o1;
                            *(float2*)&Cf[(size_t)row * N + n] = p;
                        } else {
                            Cf[(size_t)row * N + n] = o0;
                            Cf[(size_t)row * N + n + 1] = o1;
                        }
                    }
                } else if (n < N && Cf) {
                    float o0 = v0 + bias[n];
                    if (relu) o0 = fmaxf(o0, 0.f);
                    Cf[(size_t)row * N + n] = o0;
                }
            }
        }
    }
}

// ---------------- fused VQ: mu-GEMM + argmin + gather + loss, 512 threads ----------------
// smem u32 map: Mh 0..4608 | Ml 4608..9216 | (phase1 A-bufs 9216..27648 / phase2 Eh 9216, El 13824)
//               | phase1 B-bufs 27648..36864 | esq 36864..37888. Total 151552 B.
__global__ void __launch_bounds__(512, 1) vq_mma(const float* __restrict__ embed,
                                                 const float* __restrict__ mu_b)
{
    extern __shared__ uint32_t smv[];
    uint32_t* Mh = smv;
    uint32_t* Ml = smv + 4608;
    uint32_t* Eh = smv + 9216;
    uint32_t* El = smv + 13824;
    float* esq_s = (float*)(smv + 36864);

    __shared__ float sbest[16][2][2][8];
    __shared__ int   sidx[16][2][2][8];
    __shared__ int   rowidx[128];
    __shared__ float wsum[16];

    const int tid = threadIdx.x, lane = tid & 31, wid = tid >> 5;
    const int m0 = blockIdx.x * 128;
    const int wm0 = (wid >> 2) * 32;
    const int wq  = wid & 3;
    const int wn0 = wq * 32;
    const int r = lane >> 2, kq = lane & 3;
    const int prow = tid >> 4, pj = tid & 15;

    const uint32_t sbase = smem_u32(smv);
    const int g = lane >> 3, lr = lane & 7;

    // esq (region untouched by phase 1)
    #pragma unroll
    for (int i = tid; i < KCODE; i += 512) esq_s[i] = g_esq[i];

    // ===== phase 1: mu = h1p * Wm^T + mu_b (K=256, N=64) =====
    {
        // ldmatrix lane addresses (buffer 0): A at u32 9216+, B at u32 27648+
        uint32_t p1A[2], p1B;
        #pragma unroll
        for (int mt = 0; mt < 2; mt++) {
            const uint32_t row = wm0 + mt * 16 + (g & 1) * 8 + lr;
            p1A[mt] = sbase + 36864u + 4u * (row * 36 + (g >> 1) * 4);
        }
        {
            const uint32_t n = wq * 16 + (g >> 1) * 8 + lr;
            p1B = sbase + 110592u + 4u * (n * 36 + (g & 1) * 4);
        }

        float acc1[2][2][4];
        #pragma unroll
        for (int i = 0; i < 2; i++)
            #pragma unroll
            for (int j = 0; j < 2; j++)
                #pragma unroll
                for (int e = 0; e < 4; e++) acc1[i][j][e] = 0.f;

        uint4 aU[4], bU[2];
        auto pf1 = [&](int c) {
            const size_t ao = (size_t)c * 32 + 2 * pj;
            #pragma unroll
            for (int p = 0; p < 4; p++)
                aU[p] = *(const uint4*)&g_h1p[(size_t)(m0 + p * 32 + prow) * KU2 + ao];
            #pragma unroll
            for (int p = 0; p < 2; p++)
                bU[p] = *(const uint4*)&g_wmi[(size_t)(p * 32 + prow) * KU2 + ao];
        };
        auto st1 = [&](int b) {
            uint32_t* A = smv + 9216 + b * 9216;
            uint32_t* Bq = smv + 27648 + b * 4608;
            #pragma unroll
            for (int p = 0; p < 4; p++) {
                const int o = (p * 32 + prow) * 36 + 2 * pj;
                A[o] = aU[p].x; A[o + 1] = aU[p].z;
                A[4608 + o] = aU[p].y; A[4608 + o + 1] = aU[p].w;
            }
            #pragma unroll
            for (int p = 0; p < 2; p++) {
                const int o = (p * 32 + prow) * 36 + 2 * pj;
                Bq[o] = bU[p].x; Bq[o + 1] = bU[p].z;
                Bq[2304 + o] = bU[p].y; Bq[2304 + o + 1] = bU[p].w;
            }
        };
        auto cmp1 = [&](int b) {
            const uint32_t abuf = (uint32_t)b * 36864u;
            const uint32_t bbuf = (uint32_t)b * 18432u;
            #pragma unroll
            for (int ks = 0; ks < 4; ks++) {
                const uint32_t ko = ks * 32u;
                uint32_t ah[2][4], al[2][4], bh[2][2], bl[2][2];
                ldm_x4(ah[0], p1A[0] + abuf + ko);
                ldm_x4(ah[1], p1A[1] + abuf + ko);
                ldm_x4(al[0], p1A[0] + abuf + ko + 18432u);
                ldm_x4(al[1], p1A[1] + abuf + ko + 18432u);
                ldm_x4(&bh[0][0], p1B + bbuf + ko);
                ldm_x4(&bl[0][0], p1B + bbuf + ko + 9216u);
                #pragma unroll
                for (int mt = 0; mt < 2; mt++)
                    #pragma unroll
                    for (int nt = 0; nt < 2; nt++) {
                        mma16(acc1[mt][nt], ah[mt], bh[nt]);
                        mma16(acc1[mt][nt], ah[mt], bl[nt]);
                        mma16(acc1[mt][nt], al[mt], bh[nt]);
                    }
            }
        };

        pf1(0); st1(0); __syncthreads();
        for (int c = 0; c < 4; c++) {
            if (c < 3) pf1(c + 1);
            cmp1(c & 1);
            if (c < 3) st1((c + 1) & 1);
            __syncthreads();
        }

        // mu epilogue -> Mh/Ml (each (m, pair) written by exactly one thread)
        #pragma unroll
        for (int mt = 0; mt < 2; mt++)
            #pragma unroll
            for (int qq = 0; qq < 2; qq++) {
                const int m = wm0 + mt * 16 + qq * 8 + r;
                #pragma unroll
                for (int nt = 0; nt < 2; nt++) {
                    const int n = wq * 16 + nt * 8 + 2 * kq;
                    const float o0 = acc1[mt][nt][qq * 2 + 0] + mu_b[n];
                    const float o1 = acc1[mt][nt][qq * 2 + 1] + mu_b[n + 1];
                    uint32_t l; uint32_t h = split_pack(o0, o1, l);
                    Mh[m * 36 + (n >> 1)] = h;
                    Ml[m * 36 + (n >> 1)] = l;
                }
            }
    }

    // ===== phase 2: argmin over codebook (proven logic) =====
    float best[2][2];
    int   bidx[2][2];
    #pragma unroll
    for (int i = 0; i < 2; i++)
        #pragma unroll
        for (int j = 0; j < 2; j++) { best[i][j] = 3.4e38f; bidx[i][j] = 0; }

    uint32_t aM[2], aE[2];
    #pragma unroll
    for (int mt = 0; mt < 2; mt++) {
        const uint32_t row = wm0 + mt * 16 + (g & 1) * 8 + lr;
        aM[mt] = sbase + 4u * (row * 36 + (g >> 1) * 4);
    }
    #pragma unroll
    for (int np = 0; np < 2; np++) {
        const uint32_t n = wn0 + (2 * np + (g >> 1)) * 8 + lr;
        aE[np] = sbase + 4u * (9216 + n * 36 + (g & 1) * 4);
    }

    uint32_t uh[8], ul[8];
    for (int ct = 0; ct < 8; ct++) {
        #pragma unroll
        for (int ps = 0; ps < 8; ps++) {
            const int row = ps * 16 + wid;
            uh[ps] = g_eth[(size_t)(ct * 128 + row) * 32 + lane];
            ul[ps] = g_etl[(size_t)(ct * 128 + row) * 32 + lane];
        }
        __syncthreads();   // prior compute / phase-1 epilogue complete
        #pragma unroll
        for (int ps = 0; ps < 8; ps++) {
            const int row = ps * 16 + wid;
            Eh[row * 36 + lane] = uh[ps];
            El[row * 36 + lane] = ul[ps];
        }
        __syncthreads();

        float acc[2][4][4];
        #pragma unroll
        for (int i = 0; i < 2; i++)
            #pragma unroll
            for (int j = 0; j < 4; j++)
                #pragma unroll
                for (int e = 0; e < 4; e++) acc[i][j][e] = 0.f;

        #pragma unroll
        for (int ks = 0; ks < 4; ks++) {
            const uint32_t ko = ks * 32u;
            uint32_t ah[2][4], al[2][4], bh[4][2], bl[4][2];
            ldm_x4(ah[0], aM[0] + ko);
            ldm_x4(ah[1], aM[1] + ko);
            ldm_x4(al[0], aM[0] + ko + 18432u);
            ldm_x4(al[1], aM[1] + ko + 18432u);
            ldm_x4(&bh[0][0], aE[0] + ko);
            ldm_x4(&bh[2][0], aE[1] + ko);
            ldm_x4(&bl[0][0], aE[0] + ko + 18432u);
            ldm_x4(&bl[2][0], aE[1] + ko + 18432u);
            #pragma unroll
            for (int mt = 0; mt < 2; mt++)
                #pragma unroll
                for (int nt = 0; nt < 4; nt++) {
                    mma16(acc[mt][nt], ah[mt], bh[nt]);
                    mma16(acc[mt][nt], ah[mt], bl[nt]);
                    mma16(acc[mt][nt], al[mt], bh[nt]);
                }
        }

        #pragma unroll
        for (int mt = 0; mt < 2; mt++)
            #pragma unroll
            for (int q = 0; q < 2; q++)
                #pragma unroll
                for (int nt = 0; nt < 4; nt++)
                    #pragma unroll
                    for (int e = 0; e < 2; e++) {
                        const int code = ct * 128 + wn0 + nt * 8 + 2 * kq + e;
                        const float sc = esq_s[code] - 2.f * acc[mt][nt][q * 2 + e];
                        if (sc < best[mt][q]) { best[mt][q] = sc; bidx[mt][q] = code; }
                    }
        __syncthreads();
    }

    #pragma unroll
    for (int mt = 0; mt < 2; mt++)
        #pragma unroll
        for (int q = 0; q < 2; q++) {
            float b = best[mt][q]; int ix = bidx[mt][q];
            #pragma unroll
            for (int s = 1; s <= 2; s <<= 1) {
                const float ob = __shfl_xor_sync(0xffffffffu, b, s);
                const int   oi = __shfl_xor_sync(0xffffffffu, ix, s);
                if (ob < b || (ob == b && oi < ix)) { b = ob; ix = oi; }
            }
            if (kq == 0) { sbest[wid][mt][q][r] = b; sidx[wid][mt][q][r] = ix; }
        }
    __syncthreads();

    if (wq == 0 && kq == 0) {
        #pragma unroll
        for (int mt = 0; mt < 2; mt++)
            #pragma unroll
            for (int q = 0; q < 2; q++) {
                float b0 = sbest[wid][mt][q][r]; int i0 = sidx[wid][mt][q][r];
                #pragma unroll
                for (int w2 = 1; w2 < 4; w2++) {
                    float b1 = sbest[wid + w2][mt][q][r]; int i1 = sidx[wid + w2][mt][q][r];
                    if (b1 < b0 || (b1 == b0 && i1 < i0)) { b0 = b1; i0 = i1; }
                }
                rowidx[wm0 + mt * 16 + r + q * 8] = i0;
            }
    }
    __syncthreads();

    // ===== phase 3: gather q + loss partial + histogram =====
    {
        float lsum = 0.f;
        #pragma unroll
        for (int rr = 0; rr < 8; rr++) {
            const int row = wid * 8 + rr;
            const int idx = rowidx[row];
            const float e0 = embed[(size_t)(2 * lane) * KCODE + idx];
            const float e1 = embed[(size_t)(2 * lane + 1) * KCODE + idx];
            float2 qv; qv.x = e0; qv.y = e1;
            *(float2*)&g_q[(size_t)(m0 + row) * LDIM + 2 * lane] = qv;
            const __half2 H = *(const __half2*)&Mh[row * 36 + lane];
            const __half2 L = *(const __half2*)&Ml[row * 36 + lane];
            const float mu0 = __half2float(H.x) + __half2float(L.x);
            const float mu1 = __half2float(H.y) + __half2float(L.y);
            const float d0 = e0 - mu0, d1 = e1 - mu1;
            lsum += d0 * d0 + d1 * d1;
            if (lane == 0) atomicAdd(&g_counts[idx], 1);
        }
        #pragma unroll
        for (int off = 16; off; off >>= 1) lsum += __shfl_down_sync(0xffffffffu, lsum, off);
        if (lane == 0) wsum[wid] = lsum;
        __syncthreads();
        if (tid == 0) {
            float t = 0.f;
            #pragma unroll
            for (int i = 0; i < 16; i++) t += wsum[i];
            g_partials[blockIdx.x] = t;
        }
    }
}

// ---------------- prep kernels ----------------
__global__ void wsplit2(const float* __restrict__ W, uint2* __restrict__ out,
                        int N, int K, int KU, int total)
{
    int i = blockIdx.x * 256 + threadIdx.x;
    if (i >= total) return;
    int n = i / KU, j = i - n * KU;
    int k0 = 2 * j;
    float a = (n < N && k0 < K) ? W[(size_t)n * K + k0] : 0.f;
    float b = (n < N && k0 + 1 < K) ? W[(size_t)n * K + k0 + 1] : 0.f;
    uint32_t l; uint32_t h = split_pack(a, b, l);
    out[i] = make_uint2(h, l);
}
__global__ void et_split(const float* __restrict__ embed)
{
    int i = blockIdx.x * 256 + threadIdx.x;
    if (i >= KCODE * 32) return;
    int code = i >> 5, j = i & 31;
    float a = embed[(2 * j) * KCODE + code];
    float b = embed[(2 * j + 1) * KCODE + code];
    uint32_t l; uint32_t h = split_pack(a, b, l);
    g_eth[i] = h; g_etl[i] = l;
}
__global__ void esq_kernel(const float* __restrict__ embed) {
    int k = blockIdx.x * blockDim.x + threadIdx.x;
    if (k < KCODE) {
        float s = 0.f;
        #pragma unroll 8
        for (int l = 0; l < LDIM; l++) { float e = embed[l * KCODE + k]; s += e * e; }
        g_esq[k] = s;
    }
}
__global__ void zero_counts_kernel() {
    int i = blockIdx.x * blockDim.x + threadIdx.x;
    if (i < KCODE) g_counts[i] = 0;
}

__global__ void __launch_bounds__(256) finalize_kernel(float* __restrict__ out) {
    __shared__ float red[256];
    const int t = threadIdx.x;
    float s = 0.f;
    for (int i = t; i < 512; i += 256) s += g_partials[i];
    red[t] = s;
    for (int st = 128; st > 0; st >>= 1) { __syncthreads(); if (t < st) red[t] += red[t + st]; }
    __syncthreads();
    float loss = red[0] / (float)((size_t)BB * LDIM);
    __syncthreads();
    float e = 0.f;
    for (int k = t; k < KCODE; k += 256) {
        float p = (float)g_counts[k] / (float)BB;
        e += p * logf(p + 1e-10f);
    }
    red[t] = e;
    for (int st = 128; st > 0; st >>= 1) { __syncthreads(); if (t < st) red[t] += red[t + st]; }
    __syncthreads();
    if (t == 0) {
        out[(size_t)BB * FDIM] = loss;
        out[(size_t)BB * FDIM + 1] = expf(-red[0]);
    }
}

// ---------------- host launcher ----------------
#define SYM(v, s) cudaGetSymbolAddress((void**)&v, s)

extern "C" void kernel_launch(void* const* d_in, const int* in_sizes, int n_in,
                              void* d_out, int out_size)
{
    const float* x     = (const float*)d_in[0];
    const float* c     = (const float*)d_in[1];
    const float* fc1_w = (const float*)d_in[2];
    const float* fc1_b = (const float*)d_in[3];
    const float* fc2_w = (const float*)d_in[4];
    const float* fc2_b = (const float*)d_in[5];
    const float* fc3_w = (const float*)d_in[6];
    const float* fc3_b = (const float*)d_in[7];
    const float* mu_w  = (const float*)d_in[8];
    const float* mu_b  = (const float*)d_in[9];
    const float* fc4_w = (const float*)d_in[10];
    const float* fc4_b = (const float*)d_in[11];
    const float* fc5_w = (const float*)d_in[12];
    const float* fc5_b = (const float*)d_in[13];
    const float* fc6_w = (const float*)d_in[14];
    const float* fc6_b = (const float*)d_in[15];
    const float* out_w = (const float*)d_in[16];
    const float* out_b = (const float*)d_in[17];
    const float* embed = (const float*)d_in[18];
    float* out = (float*)d_out;

    float *q;
    uint2 *h1p, *h2p;
    uint2 *w1i, *w2i, *w3i, *wmi, *w4i, *w5i, *w6i, *woi;
    SYM(q, g_q);
    SYM(h1p, g_h1p); SYM(h2p, g_h2p);
    SYM(w1i, g_w1i); SYM(w2i, g_w2i); SYM(w3i, g_w3i); SYM(wmi, g_wmi);
    SYM(w4i, g_w4i); SYM(w5i, g_w5i); SYM(w6i, g_w6i); SYM(woi, g_woi);

    const int GEMM_SMEM = 2 * 18432 * 4;            // 147456 B
    const int VQ_SMEM   = 37888 * 4;                // 151552 B
    cudaFuncSetAttribute(mma_gemm<false>, cudaFuncAttributeMaxDynamicSharedMemorySize, GEMM_SMEM);
    cudaFuncSetAttribute(mma_gemm<true>,  cudaFuncAttributeMaxDynamicSharedMemorySize, GEMM_SMEM);
    cudaFuncSetAttribute(vq_mma, cudaFuncAttributeMaxDynamicSharedMemorySize, VQ_SMEM);

    const dim3 blk(512);
    const dim3 g256(2, BB / 128);
    const dim3 g267(3, BB / 128);

    // prep
    wsplit2<<<(256 * KU1 + 255) / 256, 256>>>(fc1_w, w1i, 256, 534, KU1, 256 * KU1);
    wsplit2<<<(256 * KU2 + 255) / 256, 256>>>(fc2_w, w2i, 256, 256, KU2, 256 * KU2);
    wsplit2<<<(256 * KU2 + 255) / 256, 256>>>(fc3_w, w3i, 256, 256, KU2, 256 * KU2);
    wsplit2<<<(128 * KU2 + 255) / 256, 256>>>(mu_w,  wmi, 64,  256, KU2, 128 * KU2);
    wsplit2<<<(256 * KU4 + 255) / 256, 256>>>(fc4_w, w4i, 256, 331, KU4, 256 * KU4);
    wsplit2<<<(256 * KU2 + 255) / 256, 256>>>(fc5_w, w5i, 256, 256, KU2, 256 * KU2);
    wsplit2<<<(256 * KU2 + 255) / 256, 256>>>(fc6_w, w6i, 256, 256, KU2, 256 * KU2);
    wsplit2<<<(384 * KU2 + 255) / 256, 256>>>(out_w, woi, 267, 256, KU2, 384 * KU2);
    et_split<<<(KCODE * 32 + 255) / 256, 256>>>(embed);
    esq_kernel<<<4, 256>>>(embed);
    zero_counts_kernel<<<4, 256>>>();

    // encoder
    mma_gemm<false><<<g256, blk, GEMM_SMEM>>>(x, FDIM, c, FDIM, nullptr, 0, w1i, KU1, fc1_b,
                                              nullptr, h1p, KU2, HDIM, 534, 1);
    mma_gemm<true><<<g256, blk, GEMM_SMEM>>>(nullptr, 0, nullptr, 0, h1p, KU2, w2i, KU2, fc2_b,
                                             nullptr, h2p, KU2, HDIM, HDIM, 1);
    mma_gemm<true><<<g256, blk, GEMM_SMEM>>>(nullptr, 0, nullptr, 0, h2p, KU2, w3i, KU2, fc3_b,
                                             nullptr, h1p, KU2, HDIM, HDIM, 1);

    // fused VQ: mu-GEMM + argmin + gather + loss
    vq_mma<<<BB / 128, 512, VQ_SMEM>>>(embed, mu_b);

    // decoder
    mma_gemm<false><<<g256, blk, GEMM_SMEM>>>(q, LDIM, c, FDIM, nullptr, 0, w4i, KU4, fc4_b,
                                              nullptr, h2p, KU2, HDIM, 331, 1);
    mma_gemm<true><<<g256, blk, GEMM_SMEM>>>(nullptr, 0, nullptr, 0, h2p, KU2, w5i, KU2, fc5_b,
                                             nullptr, h1p, KU2, HDIM, HDIM, 1);
    mma_gemm<true><<<g256, blk, GEMM_SMEM>>>(nullptr, 0, nullptr, 0, h1p, KU2, w6i, KU2, fc6_b,
                                             nullptr, h2p, KU2, HDIM, HDIM, 1);
    mma_gemm<true><<<g267, blk, GEMM_SMEM>>>(nullptr, 0, nullptr, 0, h2p, KU2, woi, KU2, out_b,
                                             out, nullptr, 0, FDIM, HDIM, 0);

    // scalars
    finalize_kernel<<<1, 256>>>(out);
}

// round 14
// speedup vs baseline: 1.1226x; 1.0226x over previous
#include <cuda_runtime.h>
#include <cuda_fp16.h>
#include <cstdint>
#include <math.h>

#define BB 65536
#define FDIM 267
#define HDIM 256
#define LDIM 64
#define KCODE 1024

// pair strides (uint2 per 2 K-elems), K padded to 32-pair (64-elem) chunk multiples
#define KU1 288   // fc1: K=534 -> 9 chunks (fp32 path)
#define KU2 128   // K=256 -> 4 chunks
#define KU4 192   // fc4: K=331 -> 6 chunks (fp32 path)

// ---------------- scratch (device globals) ----------------
__device__ uint2 g_h1p[BB * KU2];
__device__ uint2 g_h2p[BB * KU2];
__device__ float g_q[BB * LDIM];
__device__ float g_esq[KCODE];
__device__ int   g_counts[KCODE];
__device__ float g_partials[512];
__device__ uint32_t g_eth[KCODE * 32], g_etl[KCODE * 32];  // codebook pairs [code][l/2]
__device__ uint2 g_w1i[256 * KU1];
__device__ uint2 g_w2i[256 * KU2];
__device__ uint2 g_w3i[256 * KU2];
__device__ uint2 g_wmi[128 * KU2];
__device__ uint2 g_w4i[256 * KU4];
__device__ uint2 g_w5i[256 * KU2];
__device__ uint2 g_w6i[256 * KU2];
__device__ uint2 g_woi[384 * KU2];

// ---------------- helpers ----------------
__device__ __forceinline__ float hi32(float a) {
    return __uint_as_float(__float_as_uint(a) & 0xFFFFE000u);
}
__device__ __forceinline__ uint32_t packh(float x, float y) {
    uint32_t d;
    asm("cvt.rn.f16x2.f32 %0, %1, %2;" : "=r"(d) : "f"(y), "f"(x));
    return d;
}
__device__ __forceinline__ uint32_t split_pack(float a, float b, uint32_t& lo) {
    float ha = hi32(a), hb = hi32(b);
    lo = packh(a - ha, b - hb);
    return packh(ha, hb);
}
__device__ __forceinline__ uint32_t smem_u32(const void* p) {
    uint32_t a;
    asm("{ .reg .u64 t; cvta.to.shared.u64 t, %1; cvt.u32.u64 %0, t; }" : "=r"(a) : "l"(p));
    return a;
}
__device__ __forceinline__ void ldm_x4(uint32_t* d, uint32_t a) {
    asm volatile("ldmatrix.sync.aligned.m8n8.x4.shared.b16 {%0,%1,%2,%3}, [%4];"
        : "=r"(d[0]), "=r"(d[1]), "=r"(d[2]), "=r"(d[3]) : "r"(a));
}
__device__ __forceinline__ void mma16(float* d, const uint32_t* a, const uint32_t* b) {
    asm volatile(
        "mma.sync.aligned.m16n8k16.row.col.f32.f16.f16.f32 "
        "{%0,%1,%2,%3},{%4,%5,%6,%7},{%8,%9},{%0,%1,%2,%3};"
        : "+f"(d[0]), "+f"(d[1]), "+f"(d[2]), "+f"(d[3])
        : "r"(a[0]), "r"(a[1]), "r"(a[2]), "r"(a[3]), "r"(b[0]), "r"(b[1]));
}

// ---------------- fp16x3 HMMA GEMM, template on A-source (proven R12/R13) ----------------
template <bool PAIRS_A>
__global__ void __launch_bounds__(512, 1) mma_gemm(
    const float* __restrict__ A0, int W0,
    const float* __restrict__ A1, int W1,
    const uint2* __restrict__ Ap, int KUa,
    const uint2* __restrict__ Wt, int KUb,
    const float* __restrict__ bias,
    float* __restrict__ Cf, uint2* __restrict__ Cp, int NUp,
    int N, int K, int relu)
{
    extern __shared__ uint32_t smu[];

    const int tid = threadIdx.x, lane = tid & 31, wid = tid >> 5;
    const int m0 = blockIdx.y * 128, bn = blockIdx.x * 128;
    const int wm0 = (wid >> 2) * 32, wn0 = (wid & 3) * 32;
    const int r = lane >> 2, kq = lane & 3;
    const int NC = (K + 63) >> 6;
    const int prow = tid >> 4;
    const int pj   = tid & 15;

    const uint32_t sbase = smem_u32(smu);
    const int g = lane >> 3, lr = lane & 7;
    uint32_t aA[2], aB[2];
    #pragma unroll
    for (int mt = 0; mt < 2; mt++) {
        const uint32_t row = wm0 + mt * 16 + (g & 1) * 8 + lr;
        aA[mt] = sbase + 4u * (row * 36 + (g >> 1) * 4);
    }
    #pragma unroll
    for (int np = 0; np < 2; np++) {
        const uint32_t n = wn0 + (2 * np + (g >> 1)) * 8 + lr;
        aB[np] = sbase + 4u * (9216 + n * 36 + (g & 1) * 4);
    }

    float acc[2][4][4];
    #pragma unroll
    for (int i = 0; i < 2; i++)
        #pragma unroll
        for (int j = 0; j < 4; j++)
            #pragma unroll
            for (int e = 0; e < 4; e++) acc[i][j][e] = 0.f;

    float4 a4[4];
    uint4  aU[4];
    uint4  b4[4];

    auto prefetch = [&](int c) {
        const size_t bo = (size_t)c * 32 + 2 * pj;
        #pragma unroll
        for (int p = 0; p < 4; p++) {
            const int row = p * 32 + prow;
            if (PAIRS_A) {
                aU[p] = *(const uint4*)&Ap[(size_t)(m0 + row) * KUa + bo];
            } else {
                const int kg0 = c * 64 + 4 * pj;
                float v[4];
                #pragma unroll
                for (int e = 0; e < 4; e++) {
                    const int kg = kg0 + e;
                    float t = 0.f;
                    if (kg < K)
                        t = (kg < W0) ? A0[(size_t)(m0 + row) * W0 + kg]
                                      : A1[(size_t)(m0 + row) * W1 + (kg - W0)];
                    v[e] = t;
                }
                a4[p] = make_float4(v[0], v[1], v[2], v[3]);
            }
            b4[p] = *(const uint4*)&Wt[(size_t)(bn + row) * KUb + bo];
        }
    };
    auto store = [&](int b) {
        uint32_t* base = smu + b * 18432;
        #pragma unroll
        for (int p = 0; p < 4; p++) {
            const int o = (p * 32 + prow) * 36 + 2 * pj;
            if (PAIRS_A) {
                base[o]            = aU[p].x;
                base[o + 1]        = aU[p].z;
                base[4608 + o]     = aU[p].y;
                base[4608 + o + 1] = aU[p].w;
            } else {
                const float h0 = hi32(a4[p].x), h1 = hi32(a4[p].y);
                const float h2 = hi32(a4[p].z), h3 = hi32(a4[p].w);
                base[o]            = packh(h0, h1);
                base[o + 1]        = packh(h2, h3);
                base[4608 + o]     = packh(a4[p].x - h0, a4[p].y - h1);
                base[4608 + o + 1] = packh(a4[p].z - h2, a4[p].w - h3);
            }
            base[9216 + o]      = b4[p].x;
            base[9216 + o + 1]  = b4[p].z;
            base[13824 + o]     = b4[p].y;
            base[13824 + o + 1] = b4[p].w;
        }
    };
    auto compute = [&]() {
        #pragma unroll
        for (int ks = 0; ks < 4; ks++) {
            const uint32_t ko = ks * 32u;
            uint32_t ah[2][4], al[2][4], bh[4][2], bl[4][2];
            ldm_x4(ah[0], aA[0] + ko);
            ldm_x4(ah[1], aA[1] + ko);
            ldm_x4(al[0], aA[0] + ko + 18432u);
            ldm_x4(al[1], aA[1] + ko + 18432u);
            ldm_x4(&bh[0][0], aB[0] + ko);
            ldm_x4(&bh[2][0], aB[1] + ko);
            ldm_x4(&bl[0][0], aB[0] + ko + 18432u);
            ldm_x4(&bl[2][0], aB[1] + ko + 18432u);
            #pragma unroll
            for (int mt = 0; mt < 2; mt++)
                #pragma unroll
                for (int nt = 0; nt < 4; nt++) {
                    mma16(acc[mt][nt], ah[mt], bh[nt]);
                    mma16(acc[mt][nt], ah[mt], bl[nt]);
                    mma16(acc[mt][nt], al[mt], bh[nt]);
                }
        }
    };

    prefetch(0); store(0); __syncthreads();
    int32_t dshift = 73728;
    for (int c = 0; c < NC; c++) {
        if (c + 1 < NC) prefetch(c + 1);
        compute();
        if (c + 1 < NC) store((c + 1) & 1);
        __syncthreads();
        if (c + 1 < NC) {
            aA[0] += dshift; aA[1] += dshift;
            aB[0] += dshift; aB[1] += dshift;
            dshift = -dshift;
        }
    }

    const bool evenN = (N & 1) == 0;
    #pragma unroll
    for (int mt = 0; mt < 2; mt++) {
        #pragma unroll
        for (int q = 0; q < 2; q++) {
            const int row = m0 + wm0 + mt * 16 + q * 8 + r;
            #pragma unroll
            for (int nt = 0; nt < 4; nt++) {
                const int n = bn + wn0 + nt * 8 + 2 * kq;
                float v0 = acc[mt][nt][q * 2 + 0];
                float v1 = acc[mt][nt][q * 2 + 1];
                if (n + 1 < N) {
                    float o0 = v0 + bias[n];
                    float o1 = v1 + bias[n + 1];
                    if (relu) { o0 = fmaxf(o0, 0.f); o1 = fmaxf(o1, 0.f); }
                    if (Cp) {
                        uint32_t l; uint32_t h = split_pack(o0, o1, l);
                        Cp[(size_t)row * NUp + (n >> 1)] = make_uint2(h, l);
                    }
                    if (Cf) {
                        if (evenN) {
                            float2 p; p.x = o0; p.y = o1;
                            *(float2*)&Cf[(size_t)row * N + n] = p;
                        } else {
                            Cf[(size_t)row * N + n] = o0;
                            Cf[(size_t)row * N + n + 1] = o1;
                        }
                    }
                } else if (n < N && Cf) {
                    float o0 = v0 + bias[n];
                    if (relu) o0 = fmaxf(o0, 0.f);
                    Cf[(size_t)row * N + n] = o0;
                }
            }
        }
    }
}

// ---------------- fused VQ: mu-GEMM + argmin + gather + loss (proven R13) ----------------
__global__ void __launch_bounds__(512, 1) vq_mma(const float* __restrict__ embed,
                                                 const float* __restrict__ mu_b)
{
    extern __shared__ uint32_t smv[];
    uint32_t* Mh = smv;
    uint32_t* Ml = smv + 4608;
    uint32_t* Eh = smv + 9216;
    uint32_t* El = smv + 13824;
    float* esq_s = (float*)(smv + 36864);

    __shared__ float sbest[16][2][2][8];
    __shared__ int   sidx[16][2][2][8];
    __shared__ int   rowidx[128];
    __shared__ float wsum[16];

    const int tid = threadIdx.x, lane = tid & 31, wid = tid >> 5;
    const int m0 = blockIdx.x * 128;
    const int wm0 = (wid >> 2) * 32;
    const int wq  = wid & 3;
    const int wn0 = wq * 32;
    const int r = lane >> 2, kq = lane & 3;
    const int prow = tid >> 4, pj = tid & 15;

    const uint32_t sbase = smem_u32(smv);
    const int g = lane >> 3, lr = lane & 7;

    #pragma unroll
    for (int i = tid; i < KCODE; i += 512) esq_s[i] = g_esq[i];

    // ===== phase 1: mu = h1p * Wm^T + mu_b =====
    {
        uint32_t p1A[2], p1B;
        #pragma unroll
        for (int mt = 0; mt < 2; mt++) {
            const uint32_t row = wm0 + mt * 16 + (g & 1) * 8 + lr;
            p1A[mt] = sbase + 36864u + 4u * (row * 36 + (g >> 1) * 4);
        }
        {
            const uint32_t n = wq * 16 + (g >> 1) * 8 + lr;
            p1B = sbase + 110592u + 4u * (n * 36 + (g & 1) * 4);
        }

        float acc1[2][2][4];
        #pragma unroll
        for (int i = 0; i < 2; i++)
            #pragma unroll
            for (int j = 0; j < 2; j++)
                #pragma unroll
                for (int e = 0; e < 4; e++) acc1[i][j][e] = 0.f;

        uint4 aU[4], bU[2];
        auto pf1 = [&](int c) {
            const size_t ao = (size_t)c * 32 + 2 * pj;
            #pragma unroll
            for (int p = 0; p < 4; p++)
                aU[p] = *(const uint4*)&g_h1p[(size_t)(m0 + p * 32 + prow) * KU2 + ao];
            #pragma unroll
            for (int p = 0; p < 2; p++)
                bU[p] = *(const uint4*)&g_wmi[(size_t)(p * 32 + prow) * KU2 + ao];
        };
        auto st1 = [&](int b) {
            uint32_t* A = smv + 9216 + b * 9216;
            uint32_t* Bq = smv + 27648 + b * 4608;
            #pragma unroll
            for (int p = 0; p < 4; p++) {
                const int o = (p * 32 + prow) * 36 + 2 * pj;
                A[o] = aU[p].x; A[o + 1] = aU[p].z;
                A[4608 + o] = aU[p].y; A[4608 + o + 1] = aU[p].w;
            }
            #pragma unroll
            for (int p = 0; p < 2; p++) {
                const int o = (p * 32 + prow) * 36 + 2 * pj;
                Bq[o] = bU[p].x; Bq[o + 1] = bU[p].z;
                Bq[2304 + o] = bU[p].y; Bq[2304 + o + 1] = bU[p].w;
            }
        };
        auto cmp1 = [&](int b) {
            const uint32_t abuf = (uint32_t)b * 36864u;
            const uint32_t bbuf = (uint32_t)b * 18432u;
            #pragma unroll
            for (int ks = 0; ks < 4; ks++) {
                const uint32_t ko = ks * 32u;
                uint32_t ah[2][4], al[2][4], bh[2][2], bl[2][2];
                ldm_x4(ah[0], p1A[0] + abuf + ko);
                ldm_x4(ah[1], p1A[1] + abuf + ko);
                ldm_x4(al[0], p1A[0] + abuf + ko + 18432u);
                ldm_x4(al[1], p1A[1] + abuf + ko + 18432u);
                ldm_x4(&bh[0][0], p1B + bbuf + ko);
                ldm_x4(&bl[0][0], p1B + bbuf + ko + 9216u);
                #pragma unroll
                for (int mt = 0; mt < 2; mt++)
                    #pragma unroll
                    for (int nt = 0; nt < 2; nt++) {
                        mma16(acc1[mt][nt], ah[mt], bh[nt]);
                        mma16(acc1[mt][nt], ah[mt], bl[nt]);
                        mma16(acc1[mt][nt], al[mt], bh[nt]);
                    }
            }
        };

        pf1(0); st1(0); __syncthreads();
        for (int c = 0; c < 4; c++) {
            if (c < 3) pf1(c + 1);
            cmp1(c & 1);
            if (c < 3) st1((c + 1) & 1);
            __syncthreads();
        }

        #pragma unroll
        for (int mt = 0; mt < 2; mt++)
            #pragma unroll
            for (int qq = 0; qq < 2; qq++) {
                const int m = wm0 + mt * 16 + qq * 8 + r;
                #pragma unroll
                for (int nt = 0; nt < 2; nt++) {
                    const int n = wq * 16 + nt * 8 + 2 * kq;
                    const float o0 = acc1[mt][nt][qq * 2 + 0] + mu_b[n];
                    const float o1 = acc1[mt][nt][qq * 2 + 1] + mu_b[n + 1];
                    uint32_t l; uint32_t h = split_pack(o0, o1, l);
                    Mh[m * 36 + (n >> 1)] = h;
                    Ml[m * 36 + (n >> 1)] = l;
                }
            }
    }

    // ===== phase 2: argmin =====
    float best[2][2];
    int   bidx[2][2];
    #pragma unroll
    for (int i = 0; i < 2; i++)
        #pragma unroll
        for (int j = 0; j < 2; j++) { best[i][j] = 3.4e38f; bidx[i][j] = 0; }

    uint32_t aM[2], aE[2];
    #pragma unroll
    for (int mt = 0; mt < 2; mt++) {
        const uint32_t row = wm0 + mt * 16 + (g & 1) * 8 + lr;
        aM[mt] = sbase + 4u * (row * 36 + (g >> 1) * 4);
    }
    #pragma unroll
    for (int np = 0; np < 2; np++) {
        const uint32_t n = wn0 + (2 * np + (g >> 1)) * 8 + lr;
        aE[np] = sbase + 4u * (9216 + n * 36 + (g & 1) * 4);
    }

    uint32_t uh[8], ul[8];
    for (int ct = 0; ct < 8; ct++) {
        #pragma unroll
        for (int ps = 0; ps < 8; ps++) {
            const int row = ps * 16 + wid;
            uh[ps] = g_eth[(size_t)(ct * 128 + row) * 32 + lane];
            ul[ps] = g_etl[(size_t)(ct * 128 + row) * 32 + lane];
        }
        __syncthreads();
        #pragma unroll
        for (int ps = 0; ps < 8; ps++) {
            const int row = ps * 16 + wid;
            Eh[row * 36 + lane] = uh[ps];
            El[row * 36 + lane] = ul[ps];
        }
        __syncthreads();

        float acc[2][4][4];
        #pragma unroll
        for (int i = 0; i < 2; i++)
            #pragma unroll
            for (int j = 0; j < 4; j++)
                #pragma unroll
                for (int e = 0; e < 4; e++) acc[i][j][e] = 0.f;

        #pragma unroll
        for (int ks = 0; ks < 4; ks++) {
            const uint32_t ko = ks * 32u;
            uint32_t ah[2][4], al[2][4], bh[4][2], bl[4][2];
            ldm_x4(ah[0], aM[0] + ko);
            ldm_x4(ah[1], aM[1] + ko);
            ldm_x4(al[0], aM[0] + ko + 18432u);
            ldm_x4(al[1], aM[1] + ko + 18432u);
            ldm_x4(&bh[0][0], aE[0] + ko);
            ldm_x4(&bh[2][0], aE[1] + ko);
            ldm_x4(&bl[0][0], aE[0] + ko + 18432u);
            ldm_x4(&bl[2][0], aE[1] + ko + 18432u);
            #pragma unroll
            for (int mt = 0; mt < 2; mt++)
                #pragma unroll
                for (int nt = 0; nt < 4; nt++) {
                    mma16(acc[mt][nt], ah[mt], bh[nt]);
                    mma16(acc[mt][nt], ah[mt], bl[nt]);
                    mma16(acc[mt][nt], al[mt], bh[nt]);
                }
        }

        #pragma unroll
        for (int mt = 0; mt < 2; mt++)
            #pragma unroll
            for (int q = 0; q < 2; q++)
                #pragma unroll
                for (int nt = 0; nt < 4; nt++)
                    #pragma unroll
                    for (int e = 0; e < 2; e++) {
                        const int code = ct * 128 + wn0 + nt * 8 + 2 * kq + e;
                        const float sc = esq_s[code] - 2.f * acc[mt][nt][q * 2 + e];
                        if (sc < best[mt][q]) { best[mt][q] = sc; bidx[mt][q] = code; }
                    }
        __syncthreads();
    }

    #pragma unroll
    for (int mt = 0; mt < 2; mt++)
        #pragma unroll
        for (int q = 0; q < 2; q++) {
            float b = best[mt][q]; int ix = bidx[mt][q];
            #pragma unroll
            for (int s = 1; s <= 2; s <<= 1) {
                const float ob = __shfl_xor_sync(0xffffffffu, b, s);
                const int   oi = __shfl_xor_sync(0xffffffffu, ix, s);
                if (ob < b || (ob == b && oi < ix)) { b = ob; ix = oi; }
            }
            if (kq == 0) { sbest[wid][mt][q][r] = b; sidx[wid][mt][q][r] = ix; }
        }
    __syncthreads();

    if (wq == 0 && kq == 0) {
        #pragma unroll
        for (int mt = 0; mt < 2; mt++)
            #pragma unroll
            for (int q = 0; q < 2; q++) {
                float b0 = sbest[wid][mt][q][r]; int i0 = sidx[wid][mt][q][r];
                #pragma unroll
                for (int w2 = 1; w2 < 4; w2++) {
                    float b1 = sbest[wid + w2][mt][q][r]; int i1 = sidx[wid + w2][mt][q][r];
                    if (b1 < b0 || (b1 == b0 && i1 < i0)) { b0 = b1; i0 = i1; }
                }
                rowidx[wm0 + mt * 16 + r + q * 8] = i0;
            }
    }
    __syncthreads();

    // ===== phase 3: gather q + loss + histogram =====
    {
        float lsum = 0.f;
        #pragma unroll
        for (int rr = 0; rr < 8; rr++) {
            const int row = wid * 8 + rr;
            const int idx = rowidx[row];
            const float e0 = embed[(size_t)(2 * lane) * KCODE + idx];
            const float e1 = embed[(size_t)(2 * lane + 1) * KCODE + idx];
            float2 qv; qv.x = e0; qv.y = e1;
            *(float2*)&g_q[(size_t)(m0 + row) * LDIM + 2 * lane] = qv;
            const __half2 H = *(const __half2*)&Mh[row * 36 + lane];
            const __half2 L = *(const __half2*)&Ml[row * 36 + lane];
            const float mu0 = __half2float(H.x) + __half2float(L.x);
            const float mu1 = __half2float(H.y) + __half2float(L.y);
            const float d0 = e0 - mu0, d1 = e1 - mu1;
            lsum += d0 * d0 + d1 * d1;
            if (lane == 0) atomicAdd(&g_counts[idx], 1);
        }
        #pragma unroll
        for (int off = 16; off; off >>= 1) lsum += __shfl_down_sync(0xffffffffu, lsum, off);
        if (lane == 0) wsum[wid] = lsum;
        __syncthreads();
        if (tid == 0) {
            float t = 0.f;
            #pragma unroll
            for (int i = 0; i < 16; i++) t += wsum[i];
            g_partials[blockIdx.x] = t;
        }
    }
}

// ---------------- single fused prep kernel ----------------
// block-range dispatch over all weight splits + codebook split/esq + counts zero.
__device__ __forceinline__ void wsplit_elem(const float* __restrict__ W, uint2* __restrict__ out,
                                            int N, int K, int KU, int i)
{
    int n = i / KU, j = i - n * KU;
    int k0 = 2 * j;
    float a = (n < N && k0 < K) ? W[(size_t)n * K + k0] : 0.f;
    float b = (n < N && k0 + 1 < K) ? W[(size_t)n * K + k0 + 1] : 0.f;
    uint32_t l; uint32_t h = split_pack(a, b, l);
    out[i] = make_uint2(h, l);
}

// segment block offsets (256 threads/block; all segment sizes are multiples of 256)
#define PB_W1 0
#define PB_W2 (PB_W1 + (256 * KU1) / 256)    // 288
#define PB_W3 (PB_W2 + (256 * KU2) / 256)    // 416
#define PB_WM (PB_W3 + (256 * KU2) / 256)    // 544
#define PB_W4 (PB_WM + (128 * KU2) / 256)    // 608
#define PB_W5 (PB_W4 + (256 * KU4) / 256)    // 800
#define PB_W6 (PB_W5 + (256 * KU2) / 256)    // 928
#define PB_WO (PB_W6 + (256 * KU2) / 256)    // 1056
#define PB_ET (PB_WO + (384 * KU2) / 256)    // 1248
#define PB_ZC (PB_ET + (KCODE * 32) / 256)   // 1376
#define PB_END (PB_ZC + 4)                   // 1380

__global__ void __launch_bounds__(256) prep_all(
    const float* __restrict__ fc1_w, const float* __restrict__ fc2_w,
    const float* __restrict__ fc3_w, const float* __restrict__ mu_w,
    const float* __restrict__ fc4_w, const float* __restrict__ fc5_w,
    const float* __restrict__ fc6_w, const float* __restrict__ out_w,
    const float* __restrict__ embed)
{
    const int b = blockIdx.x, tid = threadIdx.x;
    if (b < PB_W2)      wsplit_elem(fc1_w, g_w1i, 256, 534, KU1, (b - PB_W1) * 256 + tid);
    else if (b < PB_W3) wsplit_elem(fc2_w, g_w2i, 256, 256, KU2, (b - PB_W2) * 256 + tid);
    else if (b < PB_WM) wsplit_elem(fc3_w, g_w3i, 256, 256, KU2, (b - PB_W3) * 256 + tid);
    else if (b < PB_W4) wsplit_elem(mu_w,  g_wmi, 64,  256, KU2, (b - PB_WM) * 256 + tid);
    else if (b < PB_W5) wsplit_elem(fc4_w, g_w4i, 256, 331, KU4, (b - PB_W4) * 256 + tid);
    else if (b < PB_W6) wsplit_elem(fc5_w, g_w5i, 256, 256, KU2, (b - PB_W5) * 256 + tid);
    else if (b < PB_WO) wsplit_elem(fc6_w, g_w6i, 256, 256, KU2, (b - PB_W6) * 256 + tid);
    else if (b < PB_ET) wsplit_elem(out_w, g_woi, 267, 256, KU2, (b - PB_WO) * 256 + tid);
    else if (b < PB_ZC) {
        // codebook transpose+split; one warp per code (i aligned: 32 threads/code)
        const int i = (b - PB_ET) * 256 + tid;
        const int code = i >> 5, j = i & 31;
        const float a = embed[(size_t)(2 * j) * KCODE + code];
        const float bb = embed[(size_t)(2 * j + 1) * KCODE + code];
        uint32_t l; uint32_t h = split_pack(a, bb, l);
        g_eth[i] = h; g_etl[i] = l;
        // esq via warp butterfly (deterministic: fixed tree order)
        float s = a * a + bb * bb;
        #pragma unroll
        for (int off = 16; off; off >>= 1) s += __shfl_down_sync(0xffffffffu, s, off);
        if (j == 0) g_esq[code] = s;
    } else {
        const int i = (b - PB_ZC) * 256 + tid;
        if (i < KCODE) g_counts[i] = 0;
    }
}

__global__ void __launch_bounds__(256) finalize_kernel(float* __restrict__ out) {
    __shared__ float red[256];
    const int t = threadIdx.x;
    float s = 0.f;
    for (int i = t; i < 512; i += 256) s += g_partials[i];
    red[t] = s;
    for (int st = 128; st > 0; st >>= 1) { __syncthreads(); if (t < st) red[t] += red[t + st]; }
    __syncthreads();
    float loss = red[0] / (float)((size_t)BB * LDIM);
    __syncthreads();
    float e = 0.f;
    for (int k = t; k < KCODE; k += 256) {
        float p = (float)g_counts[k] / (float)BB;
        e += p * logf(p + 1e-10f);
    }
    red[t] = e;
    for (int st = 128; st > 0; st >>= 1) { __syncthreads(); if (t < st) red[t] += red[t + st]; }
    __syncthreads();
    if (t == 0) {
        out[(size_t)BB * FDIM] = loss;
        out[(size_t)BB * FDIM + 1] = expf(-red[0]);
    }
}

// ---------------- host launcher ----------------
#define SYM(v, s) cudaGetSymbolAddress((void**)&v, s)

extern "C" void kernel_launch(void* const* d_in, const int* in_sizes, int n_in,
                              void* d_out, int out_size)
{
    const float* x     = (const float*)d_in[0];
    const float* c     = (const float*)d_in[1];
    const float* fc1_w = (const float*)d_in[2];
    const float* fc1_b = (const float*)d_in[3];
    const float* fc2_w = (const float*)d_in[4];
    const float* fc2_b = (const float*)d_in[5];
    const float* fc3_w = (const float*)d_in[6];
    const float* fc3_b = (const float*)d_in[7];
    const float* mu_w  = (const float*)d_in[8];
    const float* mu_b  = (const float*)d_in[9];
    const float* fc4_w = (const float*)d_in[10];
    const float* fc4_b = (const float*)d_in[11];
    const float* fc5_w = (const float*)d_in[12];
    const float* fc5_b = (const float*)d_in[13];
    const float* fc6_w = (const float*)d_in[14];
    const float* fc6_b = (const float*)d_in[15];
    const float* out_w = (const float*)d_in[16];
    const float* out_b = (const float*)d_in[17];
    const float* embed = (const float*)d_in[18];
    float* out = (float*)d_out;

    float *q;
    uint2 *h1p, *h2p;
    uint2 *w1i, *w2i, *w3i, *wmi, *w4i, *w5i, *w6i, *woi;
    SYM(q, g_q);
    SYM(h1p, g_h1p); SYM(h2p, g_h2p);
    SYM(w1i, g_w1i); SYM(w2i, g_w2i); SYM(w3i, g_w3i); SYM(wmi, g_wmi);
    SYM(w4i, g_w4i); SYM(w5i, g_w5i); SYM(w6i, g_w6i); SYM(woi, g_woi);

    const int GEMM_SMEM = 2 * 18432 * 4;            // 147456 B
    const int VQ_SMEM   = 37888 * 4;                // 151552 B
    cudaFuncSetAttribute(mma_gemm<false>, cudaFuncAttributeMaxDynamicSharedMemorySize, GEMM_SMEM);
    cudaFuncSetAttribute(mma_gemm<true>,  cudaFuncAttributeMaxDynamicSharedMemorySize, GEMM_SMEM);
    cudaFuncSetAttribute(vq_mma, cudaFuncAttributeMaxDynamicSharedMemorySize, VQ_SMEM);

    const dim3 blk(512);
    const dim3 g256(2, BB / 128);
    const dim3 g267(3, BB / 128);

    // single fused prep launch
    prep_all<<<PB_END, 256>>>(fc1_w, fc2_w, fc3_w, mu_w, fc4_w, fc5_w, fc6_w, out_w, embed);

    // encoder
    mma_gemm<false><<<g256, blk, GEMM_SMEM>>>(x, FDIM, c, FDIM, nullptr, 0, w1i, KU1, fc1_b,
                                              nullptr, h1p, KU2, HDIM, 534, 1);
    mma_gemm<true><<<g256, blk, GEMM_SMEM>>>(nullptr, 0, nullptr, 0, h1p, KU2, w2i, KU2, fc2_b,
                                             nullptr, h2p, KU2, HDIM, HDIM, 1);
    mma_gemm<true><<<g256, blk, GEMM_SMEM>>>(nullptr, 0, nullptr, 0, h2p, KU2, w3i, KU2, fc3_b,
                                             nullptr, h1p, KU2, HDIM, HDIM, 1);

    // fused VQ: mu-GEMM + argmin + gather + loss
    vq_mma<<<BB / 128, 512, VQ_SMEM>>>(embed, mu_b);

    // decoder
    mma_gemm<false><<<g256, blk, GEMM_SMEM>>>(q, LDIM, c, FDIM, nullptr, 0, w4i, KU4, fc4_b,
                                              nullptr, h2p, KU2, HDIM, 331, 1);
    mma_gemm<true><<<g256, blk, GEMM_SMEM>>>(nullptr, 0, nullptr, 0, h2p, KU2, w5i, KU2, fc5_b,
                                             nullptr, h1p, KU2, HDIM, HDIM, 1);
    mma_gemm<true><<<g256, blk, GEMM_SMEM>>>(nullptr, 0, nullptr, 0, h1p, KU2, w6i, KU2, fc6_b,
                                             nullptr, h2p, KU2, HDIM, HDIM, 1);
    mma_gemm<true><<<g267, blk, GEMM_SMEM>>>(nullptr, 0, nullptr, 0, h2p, KU2, woi, KU2, out_b,
                                             out, nullptr, 0, FDIM, HDIM, 0);

    // scalars
    finalize_kernel<<<1, 256>>>(out);
}